// round 11
// baseline (speedup 1.0000x reference)
#include <cuda_runtime.h>
#include <cuda_bf16.h>
#include <cstdint>

#define B_    4
#define SQ_   2048
#define SK_   2048
#define D_    1024
#define H_    16
#define HD_   64
#define SCALE_ 0.125f
#define M_TOT (B_ * SQ_)   // 8192

// ---------------------------------------------------------------------------
// Scratch (__device__ globals per allocation rules)
// ---------------------------------------------------------------------------
__device__ float g_Q  [(size_t)M_TOT * D_];
__device__ float g_KV [(size_t)M_TOT * 2 * D_];
__device__ float g_ctx[(size_t)M_TOT * D_];

__device__ __nv_bfloat16 g_qh[(size_t)M_TOT * D_], g_ql[(size_t)M_TOT * D_];
__device__ __nv_bfloat16 g_kh[(size_t)M_TOT * D_], g_kl[(size_t)M_TOT * D_];
__device__ __nv_bfloat16 g_ch[(size_t)M_TOT * D_], g_cl[(size_t)M_TOT * D_];

__device__ __nv_bfloat16 g_WqTh[D_ * D_],      g_WqTl[D_ * D_];
__device__ __nv_bfloat16 g_WkvTh[2 * D_ * D_], g_WkvTl[2 * D_ * D_];
__device__ __nv_bfloat16 g_WoTh[D_ * D_],      g_WoTl[D_ * D_];

// Per-head split arrays for attention: [b*H + h][seq][64]
__device__ __nv_bfloat16 g_Qh2[(size_t)M_TOT * D_], g_Ql2[(size_t)M_TOT * D_];
__device__ __nv_bfloat16 g_Kh2[(size_t)M_TOT * D_], g_Kl2[(size_t)M_TOT * D_];
__device__ __nv_bfloat16 g_Vh2[(size_t)M_TOT * D_], g_Vl2[(size_t)M_TOT * D_];

// ---------------------------------------------------------------------------
// Helpers
// ---------------------------------------------------------------------------
__device__ __forceinline__ uint32_t smem_u32(const void* p) {
    uint32_t a;
    asm("{ .reg .u64 t; cvta.to.shared.u64 t, %1; cvt.u32.u64 %0, t; }" : "=r"(a) : "l"(p));
    return a;
}

#define SW128(off) ((off) ^ (((off) >> 3) & 0x70))

#define CP16(dst, src) \
    asm volatile("cp.async.cg.shared.global [%0], [%1], 16;" \
                 :: "r"(dst), "l"(src) : "memory")
#define CP_COMMIT() asm volatile("cp.async.commit_group;" ::: "memory")
#define CP_WAIT1()  asm volatile("cp.async.wait_group 1;" ::: "memory")

#define LDSM_X4(r, addr) \
    asm volatile("ldmatrix.sync.aligned.m8n8.x4.shared.b16 {%0,%1,%2,%3}, [%4];" \
                 : "=r"((r)[0]), "=r"((r)[1]), "=r"((r)[2]), "=r"((r)[3]) : "r"(addr))
#define LDSM_X4_T(r, addr) \
    asm volatile("ldmatrix.sync.aligned.m8n8.x4.trans.shared.b16 {%0,%1,%2,%3}, [%4];" \
                 : "=r"((r)[0]), "=r"((r)[1]), "=r"((r)[2]), "=r"((r)[3]) : "r"(addr))

#define MMA16816(c, a, b) \
    asm volatile("mma.sync.aligned.m16n8k16.row.col.f32.bf16.bf16.f32 " \
                 "{%0,%1,%2,%3}, {%4,%5,%6,%7}, {%8,%9}, {%0,%1,%2,%3};" \
                 : "+f"((c)[0]), "+f"((c)[1]), "+f"((c)[2]), "+f"((c)[3]) \
                 : "r"((a)[0]), "r"((a)[1]), "r"((a)[2]), "r"((a)[3]), \
                   "r"((b)[0]), "r"((b)[1]))

__device__ __forceinline__ void split2(float x, float y, uint32_t& hi, uint32_t& lo) {
    __nv_bfloat162 h = __floats2bfloat162_rn(x, y);
    float hx = __bfloat162float(h.x), hy = __bfloat162float(h.y);
    __nv_bfloat162 l = __floats2bfloat162_rn(x - hx, y - hy);
    hi = reinterpret_cast<uint32_t&>(h);
    lo = reinterpret_cast<uint32_t&>(l);
}

// ---------------------------------------------------------------------------
// Prep kernels
// ---------------------------------------------------------------------------
__global__ void prep_act(const float* __restrict__ X,
                         __nv_bfloat16* __restrict__ Xh,
                         __nv_bfloat16* __restrict__ Xl, int n4) {
    int i = blockIdx.x * blockDim.x + threadIdx.x;
    int stride = gridDim.x * blockDim.x;
    for (; i < n4; i += stride) {
        float4 v = ((const float4*)X)[i];
        uint32_t h0, l0, h1, l1;
        split2(v.x, v.y, h0, l0);
        split2(v.z, v.w, h1, l1);
        ((uint32_t*)Xh)[i * 2 + 0] = h0;
        ((uint32_t*)Xh)[i * 2 + 1] = h1;
        ((uint32_t*)Xl)[i * 2 + 0] = l0;
        ((uint32_t*)Xl)[i * 2 + 1] = l1;
    }
}

__global__ void prep_wT(const float* __restrict__ W,
                        __nv_bfloat16* __restrict__ Th,
                        __nv_bfloat16* __restrict__ Tl, int Kd, int Nd) {
    __shared__ float t[32][33];
    int n  = blockIdx.x * 32 + threadIdx.x;
    int k0 = blockIdx.y * 32;
    for (int i = threadIdx.y; i < 32; i += 8)
        t[i][threadIdx.x] = W[(size_t)(k0 + i) * Nd + n];
    __syncthreads();
    int nn = blockIdx.x * 32;
    for (int i = threadIdx.y; i < 32; i += 8) {
        float v = t[threadIdx.x][i];
        __nv_bfloat16 h = __float2bfloat16_rn(v);
        Th[(size_t)(nn + i) * Kd + k0 + threadIdx.x] = h;
        Tl[(size_t)(nn + i) * Kd + k0 + threadIdx.x] =
            __float2bfloat16_rn(v - __bfloat162float(h));
    }
}

// Rearrange+split Q proj and KV proj into per-head bf16 hi/lo arrays.
__global__ void prep_split_qkv(const float* __restrict__ Q, const float* __restrict__ KV,
                               __nv_bfloat16* __restrict__ Qh, __nv_bfloat16* __restrict__ Ql,
                               __nv_bfloat16* __restrict__ Kh, __nv_bfloat16* __restrict__ Kl,
                               __nv_bfloat16* __restrict__ Vh, __nv_bfloat16* __restrict__ Vl) {
    const int total = M_TOT * D_ / 2;   // 4M
    int idx = blockIdx.x * blockDim.x + threadIdx.x;
    int stride = gridDim.x * blockDim.x;
    for (; idx < total; idx += stride) {
        int d2 = idx & 31;
        int s  = (idx >> 5) & 2047;
        int bh = idx >> 16;
        int h = bh & 15, b = bh >> 4;
        size_t qsrc = ((size_t)(b * SQ_ + s)) * D_ + h * 64 + d2 * 2;
        size_t ksrc = ((size_t)(b * SK_ + s)) * (2 * D_) + h * 64 + d2 * 2;
        float2 qv = *(const float2*)(Q + qsrc);
        float2 kv = *(const float2*)(KV + ksrc);
        float2 vv = *(const float2*)(KV + ksrc + D_);
        uint32_t hi, lo;
        split2(qv.x, qv.y, hi, lo);
        ((uint32_t*)Qh)[idx] = hi; ((uint32_t*)Ql)[idx] = lo;
        split2(kv.x, kv.y, hi, lo);
        ((uint32_t*)Kh)[idx] = hi; ((uint32_t*)Kl)[idx] = lo;
        split2(vv.x, vv.y, hi, lo);
        ((uint32_t*)Vh)[idx] = hi; ((uint32_t*)Vl)[idx] = lo;
    }
}

// ---------------------------------------------------------------------------
// Tensor-core GEMM (R5 config: 128x128 tile, BK=32, 3-stage, 2 CTA/SM).
// Only mainloop delta vs R5: B operand loaded via x4 ldmatrix (half the issues).
// ---------------------------------------------------------------------------
#define BK      32
#define STAGES  3
#define STAGE_BYTES 32768
#define GEMM_SMEM (1024 + STAGES * STAGE_BYTES)

__global__ __launch_bounds__(256, 2) void gemm_mma(
    const __nv_bfloat16* __restrict__ Ah, const __nv_bfloat16* __restrict__ Al,
    const __nv_bfloat16* __restrict__ Bh, const __nv_bfloat16* __restrict__ Bl,
    const float* __restrict__ bias, float* __restrict__ C, int N, int K)
{
    extern __shared__ char smraw[];
    const uint32_t raw32  = smem_u32(smraw);
    const uint32_t heap32 = (raw32 + 1023) & ~1023u;

    const int tid  = threadIdx.x;
    const int lane = tid & 31, wid = tid >> 5;
    const int wm0  = (wid & 3) * 32;
    const int wn0  = (wid >> 2) * 64;
    const int m0   = blockIdx.y * 128;
    const int n0   = blockIdx.x * 128;

    const bool isA = tid < 128;
    const int  lrow = isA ? tid : tid - 128;
    const __nv_bfloat16* gh = isA ? Ah + (size_t)(m0 + lrow) * K
                                  : Bh + (size_t)(n0 + lrow) * K;
    const __nv_bfloat16* gl = isA ? Al + (size_t)(m0 + lrow) * K
                                  : Bl + (size_t)(n0 + lrow) * K;
    const uint32_t dstBase = heap32 + (isA ? 0u : 16384u);
    uint32_t dsw[8];
    #pragma unroll
    for (int seg = 0; seg < 4; seg++) {
        dsw[seg]     = SW128((uint32_t)(lrow * 128 + seg * 16));
        dsw[4 + seg] = SW128((uint32_t)(lrow * 128 + 64 + seg * 16));
    }

    float acc[2][8][4];
    #pragma unroll
    for (int mt = 0; mt < 2; mt++)
        #pragma unroll
        for (int nt = 0; nt < 8; nt++)
            #pragma unroll
            for (int r = 0; r < 4; r++) acc[mt][nt][r] = 0.f;

    const uint32_t aRowOff = (uint32_t)((wm0 + (lane & 15)) * 128 + ((lane >> 4) << 4));
    const uint32_t bRowOff = (uint32_t)((wn0 + (lane & 15)) * 128 + ((lane >> 4) << 4));

    const int steps = K / BK;

    #pragma unroll
    for (int s = 0; s < 2; s++) {
        #pragma unroll
        for (int seg = 0; seg < 4; seg++) {
            CP16(dstBase + s * STAGE_BYTES + dsw[seg],     gh + s * BK + seg * 8);
            CP16(dstBase + s * STAGE_BYTES + dsw[4 + seg], gl + s * BK + seg * 8);
        }
        CP_COMMIT();
    }

    for (int i = 0; i < steps; i++) {
        CP_WAIT1();
        __syncthreads();

        if (i + 2 < steps) {
            const int s = (i + 2) % STAGES;
            const int k0 = (i + 2) * BK;
            #pragma unroll
            for (int seg = 0; seg < 4; seg++) {
                CP16(dstBase + s * STAGE_BYTES + dsw[seg],     gh + k0 + seg * 8);
                CP16(dstBase + s * STAGE_BYTES + dsw[4 + seg], gl + k0 + seg * 8);
            }
        }
        CP_COMMIT();

        const uint32_t aB = heap32 + (i % STAGES) * STAGE_BYTES;
        const uint32_t bB = aB + 16384;

        #pragma unroll
        for (int kh = 0; kh < 2; kh++) {
            uint32_t afh[2][4], afl[2][4];
            #pragma unroll
            for (int mt = 0; mt < 2; mt++) {
                uint32_t off = aRowOff + (uint32_t)(mt * 16 * 128 + kh * 32);
                LDSM_X4(afh[mt], aB + SW128(off));
                LDSM_X4(afl[mt], aB + SW128(off + 64));
            }
            #pragma unroll
            for (int p = 0; p < 4; p++) {
                uint32_t off = bRowOff + (uint32_t)(p * 16 * 128 + kh * 32);
                uint32_t b4h[4], b4l[4];
                LDSM_X4(b4h, bB + SW128(off));
                LDSM_X4(b4l, bB + SW128(off + 64));
                uint32_t bh0[2] = {b4h[0], b4h[2]}, bh1[2] = {b4h[1], b4h[3]};
                uint32_t bl0[2] = {b4l[0], b4l[2]}, bl1[2] = {b4l[1], b4l[3]};
                #pragma unroll
                for (int mt = 0; mt < 2; mt++) {
                    MMA16816(acc[mt][2 * p],     afh[mt], bh0);
                    MMA16816(acc[mt][2 * p],     afh[mt], bl0);
                    MMA16816(acc[mt][2 * p],     afl[mt], bh0);
                    MMA16816(acc[mt][2 * p + 1], afh[mt], bh1);
                    MMA16816(acc[mt][2 * p + 1], afh[mt], bl1);
                    MMA16816(acc[mt][2 * p + 1], afl[mt], bh1);
                }
            }
        }
    }

    // ---- epilogue: direct stores + bias (R5-proven) ----
    const int erow = lane >> 2, ecol = (lane & 3) * 2;
    #pragma unroll
    for (int nt = 0; nt < 8; nt++) {
        int col = n0 + wn0 + nt * 8 + ecol;
        float2 bv = *(const float2*)&bias[col];
        #pragma unroll
        for (int mt = 0; mt < 2; mt++) {
            int row = m0 + wm0 + mt * 16 + erow;
            float2 v0, v1;
            v0.x = acc[mt][nt][0] + bv.x;  v0.y = acc[mt][nt][1] + bv.y;
            v1.x = acc[mt][nt][2] + bv.x;  v1.y = acc[mt][nt][3] + bv.y;
            *(float2*)&C[(size_t)row * N + col]       = v0;
            *(float2*)&C[(size_t)(row + 8) * N + col] = v1;
        }
    }
}

// ---------------------------------------------------------------------------
// Tensor-core flash attention (exact R5 kernel)
// ---------------------------------------------------------------------------
#define ATTN_SMEM (98304 + 1024)

__global__ __launch_bounds__(256, 2) void attn_tc(
    const __nv_bfloat16* __restrict__ Qh2, const __nv_bfloat16* __restrict__ Ql2,
    const __nv_bfloat16* __restrict__ Kh2, const __nv_bfloat16* __restrict__ Kl2,
    const __nv_bfloat16* __restrict__ Vh2, const __nv_bfloat16* __restrict__ Vl2,
    float* __restrict__ ctx)
{
    extern __shared__ char smraw[];
    const uint32_t raw32  = smem_u32(smraw);
    const uint32_t heap32 = (raw32 + 1023) & ~1023u;

    const int tid  = threadIdx.x;
    const int lane = tid & 31, wid = tid >> 5;
    const int q0 = blockIdx.x * 128;
    const int h  = blockIdx.y, b = blockIdx.z;
    const int bh = b * H_ + h;
    const size_t headQ = (size_t)bh * SQ_ * 64;
    const size_t headK = (size_t)bh * SK_ * 64;

    const uint32_t QH = heap32, QL = heap32 + 16384;
    #define STG(s) (heap32 + 32768u + (uint32_t)(s) * 32768u)

    {
        const int arr = tid >> 7, r = tid & 127;
        const __nv_bfloat16* src = (arr ? Ql2 : Qh2) + headQ + (size_t)(q0 + r) * 64;
        const uint32_t dst = heap32 + (uint32_t)arr * 16384u;
        #pragma unroll
        for (int seg = 0; seg < 8; seg++)
            CP16(dst + SW128((uint32_t)(r * 128 + seg * 16)), src + seg * 8);
    }
    const int larr = tid >> 6, lrow = tid & 63;
    const __nv_bfloat16* lsrc0 =
        (larr == 0 ? Kh2 : larr == 1 ? Kl2 : larr == 2 ? Vh2 : Vl2) + headK + (size_t)lrow * 64;
    uint32_t lsw[8];
    #pragma unroll
    for (int seg = 0; seg < 8; seg++)
        lsw[seg] = (uint32_t)larr * 8192u + SW128((uint32_t)(lrow * 128 + seg * 16));

    #pragma unroll
    for (int seg = 0; seg < 8; seg++)
        CP16(STG(0) + lsw[seg], lsrc0 + seg * 8);
    CP_COMMIT();

    float oacc[8][4];
    #pragma unroll
    for (int nt = 0; nt < 8; nt++)
        #pragma unroll
        for (int r = 0; r < 4; r++) oacc[nt][r] = 0.f;
    float mrow[2] = {-1e30f, -1e30f}, lrowsum[2] = {0.f, 0.f};

    const float c2 = SCALE_ * 1.44269504088896340736f;
    const int wm = wid * 16;
    const uint32_t aOff = (uint32_t)((wm + (lane & 15)) * 128 + ((lane >> 4) << 4));
    const uint32_t kOff = (uint32_t)((lane & 15) * 128 + ((lane >> 4) << 4));
    const uint32_t vOff = (uint32_t)((lane & 15) * 128 + ((lane >> 4) << 4));

    const int iters = SK_ / 64;
    for (int i = 0; i < iters; i++) {
        __syncthreads();
        if (i + 1 < iters) {
            const __nv_bfloat16* src = lsrc0 + (size_t)(i + 1) * 64 * 64;
            const uint32_t stg = STG((i + 1) & 1);
            #pragma unroll
            for (int seg = 0; seg < 8; seg++)
                CP16(stg + lsw[seg], src + seg * 8);
        }
        CP_COMMIT();
        CP_WAIT1();
        __syncthreads();

        const uint32_t KH = STG(i & 1), KL = KH + 8192, VH = KH + 16384, VL = KH + 24576;

        float sacc[8][4];
        #pragma unroll
        for (int nt = 0; nt < 8; nt++)
            #pragma unroll
            for (int r = 0; r < 4; r++) sacc[nt][r] = 0.f;

        #pragma unroll
        for (int kc = 0; kc < 4; kc++) {
            uint32_t afh[4], afl[4];
            LDSM_X4(afh, QH + SW128(aOff + kc * 32));
            LDSM_X4(afl, QL + SW128(aOff + kc * 32));
            #pragma unroll
            for (int ntp = 0; ntp < 4; ntp++) {
                uint32_t b4h[4], b4l[4];
                uint32_t off = kOff + (uint32_t)(ntp * 2048 + kc * 32);
                LDSM_X4(b4h, KH + SW128(off));
                LDSM_X4(b4l, KL + SW128(off));
                uint32_t bh0[2] = {b4h[0], b4h[2]}, bh1[2] = {b4h[1], b4h[3]};
                uint32_t bl0[2] = {b4l[0], b4l[2]}, bl1[2] = {b4l[1], b4l[3]};
                MMA16816(sacc[2 * ntp],     afh, bh0);
                MMA16816(sacc[2 * ntp],     afh, bl0);
                MMA16816(sacc[2 * ntp],     afl, bh0);
                MMA16816(sacc[2 * ntp + 1], afh, bh1);
                MMA16816(sacc[2 * ntp + 1], afh, bl1);
                MMA16816(sacc[2 * ntp + 1], afl, bh1);
            }
        }

        float fac[2];
        #pragma unroll
        for (int j = 0; j < 2; j++) {
            float tmax = -1e30f;
            #pragma unroll
            for (int nt = 0; nt < 8; nt++)
                tmax = fmaxf(tmax, fmaxf(sacc[nt][2 * j], sacc[nt][2 * j + 1]));
            tmax = fmaxf(tmax, __shfl_xor_sync(0xffffffffu, tmax, 1));
            tmax = fmaxf(tmax, __shfl_xor_sync(0xffffffffu, tmax, 2));
            float mn = fmaxf(mrow[j], tmax);
            fac[j] = exp2f((mrow[j] - mn) * c2);
            mrow[j] = mn;
            float tsum = 0.f;
            #pragma unroll
            for (int nt = 0; nt < 8; nt++) {
                float p0 = exp2f((sacc[nt][2 * j]     - mn) * c2);
                float p1 = exp2f((sacc[nt][2 * j + 1] - mn) * c2);
                sacc[nt][2 * j] = p0; sacc[nt][2 * j + 1] = p1;
                tsum += p0 + p1;
            }
            tsum += __shfl_xor_sync(0xffffffffu, tsum, 1);
            tsum += __shfl_xor_sync(0xffffffffu, tsum, 2);
            lrowsum[j] = lrowsum[j] * fac[j] + tsum;
            #pragma unroll
            for (int nt = 0; nt < 8; nt++) {
                oacc[nt][2 * j]     *= fac[j];
                oacc[nt][2 * j + 1] *= fac[j];
            }
        }

        #pragma unroll
        for (int kc = 0; kc < 4; kc++) {
            uint32_t ah[4], al[4];
            split2(sacc[2 * kc][0],     sacc[2 * kc][1],     ah[0], al[0]);
            split2(sacc[2 * kc][2],     sacc[2 * kc][3],     ah[1], al[1]);
            split2(sacc[2 * kc + 1][0], sacc[2 * kc + 1][1], ah[2], al[2]);
            split2(sacc[2 * kc + 1][2], sacc[2 * kc + 1][3], ah[3], al[3]);
            #pragma unroll
            for (int ntp = 0; ntp < 4; ntp++) {
                uint32_t v4h[4], v4l[4];
                uint32_t off = vOff + (uint32_t)(kc * 2048 + ntp * 32);
                LDSM_X4_T(v4h, VH + SW128(off));
                LDSM_X4_T(v4l, VL + SW128(off));
                uint32_t bh0[2] = {v4h[0], v4h[1]}, bh1[2] = {v4h[2], v4h[3]};
                uint32_t bl0[2] = {v4l[0], v4l[1]}, bl1[2] = {v4l[2], v4l[3]};
                MMA16816(oacc[2 * ntp],     ah, bh0);
                MMA16816(oacc[2 * ntp],     ah, bl0);
                MMA16816(oacc[2 * ntp],     al, bh0);
                MMA16816(oacc[2 * ntp + 1], ah, bh1);
                MMA16816(oacc[2 * ntp + 1], ah, bl1);
                MMA16816(oacc[2 * ntp + 1], al, bh1);
            }
        }
    }

    const float inv0 = 1.f / lrowsum[0], inv1 = 1.f / lrowsum[1];
    const int r0 = q0 + wm + (lane >> 2);
    const int col0 = h * 64 + (lane & 3) * 2;
    #pragma unroll
    for (int nt = 0; nt < 8; nt++) {
        int col = col0 + nt * 8;
        float2 v0, v1;
        v0.x = oacc[nt][0] * inv0;  v0.y = oacc[nt][1] * inv0;
        v1.x = oacc[nt][2] * inv1;  v1.y = oacc[nt][3] * inv1;
        *(float2*)&ctx[((size_t)(b * SQ_ + r0))     * D_ + col] = v0;
        *(float2*)&ctx[((size_t)(b * SQ_ + r0 + 8)) * D_ + col] = v1;
    }
}

// ---------------------------------------------------------------------------
extern "C" void kernel_launch(void* const* d_in, const int* in_sizes, int n_in,
                              void* d_out, int out_size)
{
    const float* query     = (const float*)d_in[0];
    const float* key_value = (const float*)d_in[1];
    const float* Wq        = (const float*)d_in[2];
    const float* bq        = (const float*)d_in[3];
    const float* Wkv       = (const float*)d_in[4];
    const float* bkv       = (const float*)d_in[5];
    const float* Wo        = (const float*)d_in[6];
    const float* bo        = (const float*)d_in[7];
    float* out = (float*)d_out;

    float *Qb, *KVb, *Ctx;
    __nv_bfloat16 *qh, *ql, *kh, *kl, *ch, *cl;
    __nv_bfloat16 *WqTh, *WqTl, *WkvTh, *WkvTl, *WoTh, *WoTl;
    __nv_bfloat16 *Qh2, *Ql2, *Kh2, *Kl2, *Vh2, *Vl2;
    cudaGetSymbolAddress((void**)&Qb,   g_Q);
    cudaGetSymbolAddress((void**)&KVb,  g_KV);
    cudaGetSymbolAddress((void**)&Ctx,  g_ctx);
    cudaGetSymbolAddress((void**)&qh,   g_qh);   cudaGetSymbolAddress((void**)&ql, g_ql);
    cudaGetSymbolAddress((void**)&kh,   g_kh);   cudaGetSymbolAddress((void**)&kl, g_kl);
    cudaGetSymbolAddress((void**)&ch,   g_ch);   cudaGetSymbolAddress((void**)&cl, g_cl);
    cudaGetSymbolAddress((void**)&WqTh, g_WqTh); cudaGetSymbolAddress((void**)&WqTl, g_WqTl);
    cudaGetSymbolAddress((void**)&WkvTh,g_WkvTh);cudaGetSymbolAddress((void**)&WkvTl,g_WkvTl);
    cudaGetSymbolAddress((void**)&WoTh, g_WoTh); cudaGetSymbolAddress((void**)&WoTl, g_WoTl);
    cudaGetSymbolAddress((void**)&Qh2,  g_Qh2);  cudaGetSymbolAddress((void**)&Ql2, g_Ql2);
    cudaGetSymbolAddress((void**)&Kh2,  g_Kh2);  cudaGetSymbolAddress((void**)&Kl2, g_Kl2);
    cudaGetSymbolAddress((void**)&Vh2,  g_Vh2);  cudaGetSymbolAddress((void**)&Vl2, g_Vl2);

    cudaFuncSetAttribute(gemm_mma, cudaFuncAttributeMaxDynamicSharedMemorySize, GEMM_SMEM);
    cudaFuncSetAttribute(attn_tc,  cudaFuncAttributeMaxDynamicSharedMemorySize, ATTN_SMEM);

    // Ordered so my launch idx 3 = gemm_mma(Q)  (ncu -s 5 window, ~2 harness
    // launches precede).  Dependencies preserved.
    prep_act<<<2048, 256>>>(query, qh, ql, M_TOT * D_ / 4);                      // 0
    prep_wT<<<dim3(D_ / 32, D_ / 32), dim3(32, 8)>>>(Wq, WqTh, WqTl, D_, D_);    // 1
    prep_act<<<2048, 256>>>(key_value, kh, kl, M_TOT * D_ / 4);                  // 2

    gemm_mma<<<dim3(D_ / 128, M_TOT / 128), 256, GEMM_SMEM>>>(                   // 3
        qh, ql, WqTh, WqTl, bq, Qb, D_, D_);

    prep_wT<<<dim3(2 * D_ / 32, D_ / 32), dim3(32, 8)>>>(Wkv, WkvTh, WkvTl,      // 4
                                                         D_, 2 * D_);
    gemm_mma<<<dim3(2 * D_ / 128, M_TOT / 128), 256, GEMM_SMEM>>>(               // 5
        kh, kl, WkvTh, WkvTl, bkv, KVb, 2 * D_, D_);

    prep_wT<<<dim3(D_ / 32, D_ / 32), dim3(32, 8)>>>(Wo, WoTh, WoTl, D_, D_);    // 6
    prep_split_qkv<<<2048, 256>>>(Qb, KVb, Qh2, Ql2, Kh2, Kl2, Vh2, Vl2);        // 7

    attn_tc<<<dim3(SQ_ / 128, H_, B_), 256, ATTN_SMEM>>>(                        // 8
        Qh2, Ql2, Kh2, Kl2, Vh2, Vl2, Ctx);

    prep_act<<<2048, 256>>>(Ctx, ch, cl, M_TOT * D_ / 4);                        // 9
    gemm_mma<<<dim3(D_ / 128, M_TOT / 128), 256, GEMM_SMEM>>>(                   // 10
        ch, cl, WoTh, WoTl, bo, out, D_, D_);
}

// round 12
// speedup vs baseline: 2.1564x; 2.1564x over previous
#include <cuda_runtime.h>
#include <cuda_bf16.h>
#include <cstdint>

#define B_    4
#define SQ_   2048
#define SK_   2048
#define D_    1024
#define H_    16
#define HD_   64
#define SCALE_ 0.125f
#define M_TOT (B_ * SQ_)   // 8192
#define KSTEPS (D_ / 32)   // 32

// ---------------------------------------------------------------------------
// Scratch (__device__ globals per allocation rules)
// ---------------------------------------------------------------------------
__device__ float g_Q  [(size_t)M_TOT * D_];
__device__ float g_KV [(size_t)M_TOT * 2 * D_];
__device__ float g_ctx[(size_t)M_TOT * D_];

// Pre-swizzled GEMM operand blocks: [tile][k_step] x 16KB, byte-identical to
// the smem stage image (128 rows x [hi 64B | lo 64B], SW128 swizzled).
__device__ __nv_bfloat16 g_qA [(size_t)2 * M_TOT * D_];
__device__ __nv_bfloat16 g_kA [(size_t)2 * M_TOT * D_];
__device__ __nv_bfloat16 g_cA [(size_t)2 * M_TOT * D_];
__device__ __nv_bfloat16 g_WqB [2 * D_ * D_];
__device__ __nv_bfloat16 g_WkvB[2 * D_ * 2 * D_];
__device__ __nv_bfloat16 g_WoB [2 * D_ * D_];

// Per-head split arrays for attention: [b*H + h][seq][64]
__device__ __nv_bfloat16 g_Qh2[(size_t)M_TOT * D_], g_Ql2[(size_t)M_TOT * D_];
__device__ __nv_bfloat16 g_Kh2[(size_t)M_TOT * D_], g_Kl2[(size_t)M_TOT * D_];
__device__ __nv_bfloat16 g_Vh2[(size_t)M_TOT * D_], g_Vl2[(size_t)M_TOT * D_];

// ---------------------------------------------------------------------------
// Helpers
// ---------------------------------------------------------------------------
__device__ __forceinline__ uint32_t smem_u32(const void* p) {
    uint32_t a;
    asm("{ .reg .u64 t; cvta.to.shared.u64 t, %1; cvt.u32.u64 %0, t; }" : "=r"(a) : "l"(p));
    return a;
}

#define SW128(off) ((off) ^ (((off) >> 3) & 0x70))

#define CP16(dst, src) \
    asm volatile("cp.async.cg.shared.global [%0], [%1], 16;" \
                 :: "r"(dst), "l"(src) : "memory")
#define CP_COMMIT() asm volatile("cp.async.commit_group;" ::: "memory")
#define CP_WAIT1()  asm volatile("cp.async.wait_group 1;" ::: "memory")

// Bulk async copy (sm_90+ base PTX): one instruction moves `bytes` linearly,
// completion signaled on mbarrier via complete_tx.
#define CP_BULK(dst, src, bytes, mbar) \
    asm volatile("cp.async.bulk.shared::cta.global.mbarrier::complete_tx::bytes " \
                 "[%0], [%1], %2, [%3];" \
                 :: "r"(dst), "l"(src), "r"(bytes), "r"(mbar) : "memory")

#define MBARRIER_INIT(addr, cnt) \
    asm volatile("mbarrier.init.shared.b64 [%0], %1;" \
                 :: "r"((uint32_t)(addr)), "r"((uint32_t)(cnt)) : "memory")
#define MBARRIER_EXPECT_TX(addr, bytes) \
    asm volatile("mbarrier.arrive.expect_tx.shared.b64 _, [%0], %1;" \
                 :: "r"((uint32_t)(addr)), "r"((uint32_t)(bytes)) : "memory")

#define MBARRIER_WAIT_PARITY(addr, parity) do {                                   \
    uint32_t _m = (uint32_t)(addr);  uint32_t _p = (uint32_t)(parity);            \
    uint32_t _d;                                                                  \
    asm volatile("{\n\t.reg .pred p;\n\t"                                         \
        "mbarrier.try_wait.parity.acquire.cta.shared::cta.b64 p, [%1], %2;\n\t"   \
        "selp.b32 %0, 1, 0, p;\n\t}" : "=r"(_d) : "r"(_m), "r"(_p) : "memory");   \
    if (!_d) {                                                                    \
        asm volatile("{\n\t.reg .pred P1;\n\t"                                    \
            "WL_%=:\n\t"                                                          \
            "mbarrier.try_wait.parity.acquire.cta.shared::cta.b64 P1, [%0], %1, 0x989680;\n\t" \
            "@P1 bra.uni WD_%=;\n\t"                                              \
            "bra.uni WL_%=;\n\t"                                                  \
            "WD_%=:\n\t}" :: "r"(_m), "r"(_p) : "memory");                        \
    }                                                                             \
} while (0)

#define LDSM_X4(r, addr) \
    asm volatile("ldmatrix.sync.aligned.m8n8.x4.shared.b16 {%0,%1,%2,%3}, [%4];" \
                 : "=r"((r)[0]), "=r"((r)[1]), "=r"((r)[2]), "=r"((r)[3]) : "r"(addr))
#define LDSM_X4_T(r, addr) \
    asm volatile("ldmatrix.sync.aligned.m8n8.x4.trans.shared.b16 {%0,%1,%2,%3}, [%4];" \
                 : "=r"((r)[0]), "=r"((r)[1]), "=r"((r)[2]), "=r"((r)[3]) : "r"(addr))
#define LDSM_X2(r, addr) \
    asm volatile("ldmatrix.sync.aligned.m8n8.x2.shared.b16 {%0,%1}, [%2];" \
                 : "=r"((r)[0]), "=r"((r)[1]) : "r"(addr))

#define MMA16816(c, a, b) \
    asm volatile("mma.sync.aligned.m16n8k16.row.col.f32.bf16.bf16.f32 " \
                 "{%0,%1,%2,%3}, {%4,%5,%6,%7}, {%8,%9}, {%0,%1,%2,%3};" \
                 : "+f"((c)[0]), "+f"((c)[1]), "+f"((c)[2]), "+f"((c)[3]) \
                 : "r"((a)[0]), "r"((a)[1]), "r"((a)[2]), "r"((a)[3]), \
                   "r"((b)[0]), "r"((b)[1]))

__device__ __forceinline__ void split2(float x, float y, uint32_t& hi, uint32_t& lo) {
    __nv_bfloat162 h = __floats2bfloat162_rn(x, y);
    float hx = __bfloat162float(h.x), hy = __bfloat162float(h.y);
    __nv_bfloat162 l = __floats2bfloat162_rn(x - hx, y - hy);
    hi = reinterpret_cast<uint32_t&>(h);
    lo = reinterpret_cast<uint32_t&>(l);
}

// ---------------------------------------------------------------------------
// Prep: fp32 activations [M][1024] -> tiled pre-swizzled blocks
//   block(mtile, kstep) = 16KB: row r, hi bf16 of k=kstep*32+kk at byte
//   (r*128 + kk*2) ^ ((r&7)<<4), lo at +64 before XOR.
// ---------------------------------------------------------------------------
__global__ void prep_act_tiled(const float* __restrict__ X,
                               __nv_bfloat16* __restrict__ out, int n4) {
    int idx = blockIdx.x * blockDim.x + threadIdx.x;
    int stride = gridDim.x * blockDim.x;
    for (; idx < n4; idx += stride) {
        int m  = idx >> 8;            // / 256 (1024/4)
        int k  = (idx & 255) << 2;
        float4 v = ((const float4*)X)[idx];
        uint32_t h0, l0, h1, l1;
        split2(v.x, v.y, h0, l0);
        split2(v.z, v.w, h1, l1);
        int mt = m >> 7, r = m & 127, ks = k >> 5, kk = k & 31;
        char* base = (char*)out + ((size_t)(mt * KSTEPS + ks)) * 16384;
        uint32_t sw = ((uint32_t)(r & 7)) << 4;
        uint32_t dh = (uint32_t)(r * 128 + kk * 2);
        uint2 hv; hv.x = h0; hv.y = h1;
        uint2 lv; lv.x = l0; lv.y = l1;
        *(uint2*)(base + (dh ^ sw))        = hv;   // dh 8-aligned; sw bits 4-6
        *(uint2*)(base + ((dh + 64) ^ sw)) = lv;
    }
}

// Weights W[K][N] -> transposed tiled pre-swizzled blocks (rows = N dim)
__global__ void prep_wT_tiled(const float* __restrict__ W,
                              __nv_bfloat16* __restrict__ out, int Kd, int Nd) {
    __shared__ float t[32][33];
    int n  = blockIdx.x * 32 + threadIdx.x;
    int k0 = blockIdx.y * 32;
    for (int i = threadIdx.y; i < 32; i += 8)
        t[i][threadIdx.x] = W[(size_t)(k0 + i) * Nd + n];
    __syncthreads();
    int nn = blockIdx.x * 32;
    int kcol = k0 + threadIdx.x;
    int ks = kcol >> 5, kk = kcol & 31;
    for (int i = threadIdx.y; i < 32; i += 8) {
        float v = t[threadIdx.x][i];
        __nv_bfloat16 h = __float2bfloat16_rn(v);
        __nv_bfloat16 l = __float2bfloat16_rn(v - __bfloat162float(h));
        int nrow = nn + i;
        int ntile = nrow >> 7, r = nrow & 127;
        char* base = (char*)out + ((size_t)(ntile * KSTEPS + ks)) * 16384;
        uint32_t sw = ((uint32_t)(r & 7)) << 4;
        uint32_t dh = (uint32_t)(r * 128 + kk * 2);
        *(__nv_bfloat16*)(base + (dh ^ sw))        = h;
        *(__nv_bfloat16*)(base + ((dh + 64) ^ sw)) = l;
    }
}

// Rearrange+split Q proj and KV proj into per-head bf16 hi/lo arrays (R5).
__global__ void prep_split_qkv(const float* __restrict__ Q, const float* __restrict__ KV,
                               __nv_bfloat16* __restrict__ Qh, __nv_bfloat16* __restrict__ Ql,
                               __nv_bfloat16* __restrict__ Kh, __nv_bfloat16* __restrict__ Kl,
                               __nv_bfloat16* __restrict__ Vh, __nv_bfloat16* __restrict__ Vl) {
    const int total = M_TOT * D_ / 2;
    int idx = blockIdx.x * blockDim.x + threadIdx.x;
    int stride = gridDim.x * blockDim.x;
    for (; idx < total; idx += stride) {
        int d2 = idx & 31;
        int s  = (idx >> 5) & 2047;
        int bh = idx >> 16;
        int h = bh & 15, b = bh >> 4;
        size_t qsrc = ((size_t)(b * SQ_ + s)) * D_ + h * 64 + d2 * 2;
        size_t ksrc = ((size_t)(b * SK_ + s)) * (2 * D_) + h * 64 + d2 * 2;
        float2 qv = *(const float2*)(Q + qsrc);
        float2 kv = *(const float2*)(KV + ksrc);
        float2 vv = *(const float2*)(KV + ksrc + D_);
        uint32_t hi, lo;
        split2(qv.x, qv.y, hi, lo);
        ((uint32_t*)Qh)[idx] = hi; ((uint32_t*)Ql)[idx] = lo;
        split2(kv.x, kv.y, hi, lo);
        ((uint32_t*)Kh)[idx] = hi; ((uint32_t*)Kl)[idx] = lo;
        split2(vv.x, vv.y, hi, lo);
        ((uint32_t*)Vh)[idx] = hi; ((uint32_t*)Vl)[idx] = lo;
    }
}

// ---------------------------------------------------------------------------
// GEMM with bulk-copy loads: compute = exact R5 mainloop (x2 B-ldsm).
// Stages filled by ONE cp.async.bulk per operand (16KB), mbarrier-gated.
// ---------------------------------------------------------------------------
#define STAGES  3
#define STAGE_BYTES 32768
#define GEMM_SMEM (2048 + STAGES * STAGE_BYTES)

__global__ __launch_bounds__(256, 2) void gemm_bulk(
    const __nv_bfloat16* __restrict__ gA, const __nv_bfloat16* __restrict__ gB,
    const float* __restrict__ bias, float* __restrict__ C, int N, int K)
{
    extern __shared__ char smraw[];
    const uint32_t raw32  = smem_u32(smraw);
    const uint32_t hdr32  = (raw32 + 1023) & ~1023u;   // mbarriers here
    const uint32_t stg32  = hdr32 + 1024;              // stages (1024-aligned)

    const int tid  = threadIdx.x;
    const int lane = tid & 31, wid = tid >> 5;
    const int wm0  = (wid & 3) * 32;
    const int wn0  = (wid >> 2) * 64;
    const int m0   = blockIdx.y * 128;
    const int n0   = blockIdx.x * 128;

    const int steps = K / 32;
    const char* srcA = (const char*)gA + (size_t)(blockIdx.y * steps) * 16384;
    const char* srcB = (const char*)gB + (size_t)(blockIdx.x * steps) * 16384;

    if (tid == 0) {
        MBARRIER_INIT(hdr32 + 0, 1);
        MBARRIER_INIT(hdr32 + 8, 1);
        MBARRIER_INIT(hdr32 + 16, 1);
    }
    __syncthreads();
    if (tid == 0) {
        #pragma unroll
        for (int s = 0; s < 2; s++) {
            MBARRIER_EXPECT_TX(hdr32 + s * 8, 32768u);
            CP_BULK(stg32 + s * STAGE_BYTES,          srcA + (size_t)s * 16384, 16384u, hdr32 + s * 8);
            CP_BULK(stg32 + s * STAGE_BYTES + 16384u, srcB + (size_t)s * 16384, 16384u, hdr32 + s * 8);
        }
    }

    float acc[2][8][4];
    #pragma unroll
    for (int mt = 0; mt < 2; mt++)
        #pragma unroll
        for (int nt = 0; nt < 8; nt++)
            #pragma unroll
            for (int r = 0; r < 4; r++) acc[mt][nt][r] = 0.f;

    const uint32_t aRowOff = (uint32_t)((wm0 + (lane & 15)) * 128 + ((lane >> 4) << 4));
    const uint32_t bRowOff = (uint32_t)((wn0 + (lane & 7)) * 128 + (((lane >> 3) & 1) << 4));

    for (int i = 0; i < steps; i++) {
        __syncthreads();   // readers of buf (i+2)%3 (iter i-1) done; orders prologue too
        if (tid == 0 && i + 2 < steps) {
            const int s = (i + 2) % STAGES;
            MBARRIER_EXPECT_TX(hdr32 + s * 8, 32768u);
            CP_BULK(stg32 + s * STAGE_BYTES,          srcA + (size_t)(i + 2) * 16384, 16384u, hdr32 + s * 8);
            CP_BULK(stg32 + s * STAGE_BYTES + 16384u, srcB + (size_t)(i + 2) * 16384, 16384u, hdr32 + s * 8);
        }
        MBARRIER_WAIT_PARITY(hdr32 + (i % STAGES) * 8, (i / STAGES) & 1);

        const uint32_t aB = stg32 + (i % STAGES) * STAGE_BYTES;
        const uint32_t bB = aB + 16384;

        #pragma unroll
        for (int kh = 0; kh < 2; kh++) {
            uint32_t afh[2][4], afl[2][4];
            #pragma unroll
            for (int mt = 0; mt < 2; mt++) {
                uint32_t off = aRowOff + (uint32_t)(mt * 16 * 128 + kh * 32);
                LDSM_X4(afh[mt], aB + SW128(off));
                LDSM_X4(afl[mt], aB + SW128(off + 64));
            }
            #pragma unroll
            for (int nt = 0; nt < 8; nt++) {
                uint32_t off = bRowOff + (uint32_t)(nt * 8 * 128 + kh * 32);
                uint32_t bfh[2], bfl[2];
                LDSM_X2(bfh, bB + SW128(off));
                LDSM_X2(bfl, bB + SW128(off + 64));
                #pragma unroll
                for (int mt = 0; mt < 2; mt++) {
                    MMA16816(acc[mt][nt], afh[mt], bfh);
                    MMA16816(acc[mt][nt], afh[mt], bfl);
                    MMA16816(acc[mt][nt], afl[mt], bfh);
                }
            }
        }
    }

    // epilogue: direct stores + bias (R5-proven)
    const int erow = lane >> 2, ecol = (lane & 3) * 2;
    #pragma unroll
    for (int nt = 0; nt < 8; nt++) {
        int col = n0 + wn0 + nt * 8 + ecol;
        float2 bv = *(const float2*)&bias[col];
        #pragma unroll
        for (int mt = 0; mt < 2; mt++) {
            int row = m0 + wm0 + mt * 16 + erow;
            float2 v0, v1;
            v0.x = acc[mt][nt][0] + bv.x;  v0.y = acc[mt][nt][1] + bv.y;
            v1.x = acc[mt][nt][2] + bv.x;  v1.y = acc[mt][nt][3] + bv.y;
            *(float2*)&C[(size_t)row * N + col]       = v0;
            *(float2*)&C[(size_t)(row + 8) * N + col] = v1;
        }
    }
}

// ---------------------------------------------------------------------------
// Tensor-core flash attention (exact R5 kernel)
// ---------------------------------------------------------------------------
#define ATTN_SMEM (98304 + 1024)

__global__ __launch_bounds__(256, 2) void attn_tc(
    const __nv_bfloat16* __restrict__ Qh2, const __nv_bfloat16* __restrict__ Ql2,
    const __nv_bfloat16* __restrict__ Kh2, const __nv_bfloat16* __restrict__ Kl2,
    const __nv_bfloat16* __restrict__ Vh2, const __nv_bfloat16* __restrict__ Vl2,
    float* __restrict__ ctx)
{
    extern __shared__ char smraw[];
    const uint32_t raw32  = smem_u32(smraw);
    const uint32_t heap32 = (raw32 + 1023) & ~1023u;

    const int tid  = threadIdx.x;
    const int lane = tid & 31, wid = tid >> 5;
    const int q0 = blockIdx.x * 128;
    const int h  = blockIdx.y, b = blockIdx.z;
    const int bh = b * H_ + h;
    const size_t headQ = (size_t)bh * SQ_ * 64;
    const size_t headK = (size_t)bh * SK_ * 64;

    const uint32_t QH = heap32, QL = heap32 + 16384;
    #define STG(s) (heap32 + 32768u + (uint32_t)(s) * 32768u)

    {
        const int arr = tid >> 7, r = tid & 127;
        const __nv_bfloat16* src = (arr ? Ql2 : Qh2) + headQ + (size_t)(q0 + r) * 64;
        const uint32_t dst = heap32 + (uint32_t)arr * 16384u;
        #pragma unroll
        for (int seg = 0; seg < 8; seg++)
            CP16(dst + SW128((uint32_t)(r * 128 + seg * 16)), src + seg * 8);
    }
    const int larr = tid >> 6, lrow = tid & 63;
    const __nv_bfloat16* lsrc0 =
        (larr == 0 ? Kh2 : larr == 1 ? Kl2 : larr == 2 ? Vh2 : Vl2) + headK + (size_t)lrow * 64;
    uint32_t lsw[8];
    #pragma unroll
    for (int seg = 0; seg < 8; seg++)
        lsw[seg] = (uint32_t)larr * 8192u + SW128((uint32_t)(lrow * 128 + seg * 16));

    #pragma unroll
    for (int seg = 0; seg < 8; seg++)
        CP16(STG(0) + lsw[seg], lsrc0 + seg * 8);
    CP_COMMIT();

    float oacc[8][4];
    #pragma unroll
    for (int nt = 0; nt < 8; nt++)
        #pragma unroll
        for (int r = 0; r < 4; r++) oacc[nt][r] = 0.f;
    float mrow[2] = {-1e30f, -1e30f}, lrowsum[2] = {0.f, 0.f};

    const float c2 = SCALE_ * 1.44269504088896340736f;
    const int wm = wid * 16;
    const uint32_t aOff = (uint32_t)((wm + (lane & 15)) * 128 + ((lane >> 4) << 4));
    const uint32_t kOff = (uint32_t)((lane & 15) * 128 + ((lane >> 4) << 4));
    const uint32_t vOff = (uint32_t)((lane & 15) * 128 + ((lane >> 4) << 4));

    const int iters = SK_ / 64;
    for (int i = 0; i < iters; i++) {
        __syncthreads();
        if (i + 1 < iters) {
            const __nv_bfloat16* src = lsrc0 + (size_t)(i + 1) * 64 * 64;
            const uint32_t stg = STG((i + 1) & 1);
            #pragma unroll
            for (int seg = 0; seg < 8; seg++)
                CP16(stg + lsw[seg], src + seg * 8);
        }
        CP_COMMIT();
        CP_WAIT1();
        __syncthreads();

        const uint32_t KH = STG(i & 1), KL = KH + 8192, VH = KH + 16384, VL = KH + 24576;

        float sacc[8][4];
        #pragma unroll
        for (int nt = 0; nt < 8; nt++)
            #pragma unroll
            for (int r = 0; r < 4; r++) sacc[nt][r] = 0.f;

        #pragma unroll
        for (int kc = 0; kc < 4; kc++) {
            uint32_t afh[4], afl[4];
            LDSM_X4(afh, QH + SW128(aOff + kc * 32));
            LDSM_X4(afl, QL + SW128(aOff + kc * 32));
            #pragma unroll
            for (int ntp = 0; ntp < 4; ntp++) {
                uint32_t b4h[4], b4l[4];
                uint32_t off = kOff + (uint32_t)(ntp * 2048 + kc * 32);
                LDSM_X4(b4h, KH + SW128(off));
                LDSM_X4(b4l, KL + SW128(off));
                uint32_t bh0[2] = {b4h[0], b4h[2]}, bh1[2] = {b4h[1], b4h[3]};
                uint32_t bl0[2] = {b4l[0], b4l[2]}, bl1[2] = {b4l[1], b4l[3]};
                MMA16816(sacc[2 * ntp],     afh, bh0);
                MMA16816(sacc[2 * ntp],     afh, bl0);
                MMA16816(sacc[2 * ntp],     afl, bh0);
                MMA16816(sacc[2 * ntp + 1], afh, bh1);
                MMA16816(sacc[2 * ntp + 1], afh, bl1);
                MMA16816(sacc[2 * ntp + 1], afl, bh1);
            }
        }

        float fac[2];
        #pragma unroll
        for (int j = 0; j < 2; j++) {
            float tmax = -1e30f;
            #pragma unroll
            for (int nt = 0; nt < 8; nt++)
                tmax = fmaxf(tmax, fmaxf(sacc[nt][2 * j], sacc[nt][2 * j + 1]));
            tmax = fmaxf(tmax, __shfl_xor_sync(0xffffffffu, tmax, 1));
            tmax = fmaxf(tmax, __shfl_xor_sync(0xffffffffu, tmax, 2));
            float mn = fmaxf(mrow[j], tmax);
            fac[j] = exp2f((mrow[j] - mn) * c2);
            mrow[j] = mn;
            float tsum = 0.f;
            #pragma unroll
            for (int nt = 0; nt < 8; nt++) {
                float p0 = exp2f((sacc[nt][2 * j]     - mn) * c2);
                float p1 = exp2f((sacc[nt][2 * j + 1] - mn) * c2);
                sacc[nt][2 * j] = p0; sacc[nt][2 * j + 1] = p1;
                tsum += p0 + p1;
            }
            tsum += __shfl_xor_sync(0xffffffffu, tsum, 1);
            tsum += __shfl_xor_sync(0xffffffffu, tsum, 2);
            lrowsum[j] = lrowsum[j] * fac[j] + tsum;
            #pragma unroll
            for (int nt = 0; nt < 8; nt++) {
                oacc[nt][2 * j]     *= fac[j];
                oacc[nt][2 * j + 1] *= fac[j];
            }
        }

        #pragma unroll
        for (int kc = 0; kc < 4; kc++) {
            uint32_t ah[4], al[4];
            split2(sacc[2 * kc][0],     sacc[2 * kc][1],     ah[0], al[0]);
            split2(sacc[2 * kc][2],     sacc[2 * kc][3],     ah[1], al[1]);
            split2(sacc[2 * kc + 1][0], sacc[2 * kc + 1][1], ah[2], al[2]);
            split2(sacc[2 * kc + 1][2], sacc[2 * kc + 1][3], ah[3], al[3]);
            #pragma unroll
            for (int ntp = 0; ntp < 4; ntp++) {
                uint32_t v4h[4], v4l[4];
                uint32_t off = vOff + (uint32_t)(kc * 2048 + ntp * 32);
                LDSM_X4_T(v4h, VH + SW128(off));
                LDSM_X4_T(v4l, VL + SW128(off));
                uint32_t bh0[2] = {v4h[0], v4h[1]}, bh1[2] = {v4h[2], v4h[3]};
                uint32_t bl0[2] = {v4l[0], v4l[1]}, bl1[2] = {v4l[2], v4l[3]};
                MMA16816(oacc[2 * ntp],     ah, bh0);
                MMA16816(oacc[2 * ntp],     ah, bl0);
                MMA16816(oacc[2 * ntp],     al, bh0);
                MMA16816(oacc[2 * ntp + 1], ah, bh1);
                MMA16816(oacc[2 * ntp + 1], ah, bl1);
                MMA16816(oacc[2 * ntp + 1], al, bh1);
            }
        }
    }

    const float inv0 = 1.f / lrowsum[0], inv1 = 1.f / lrowsum[1];
    const int r0 = q0 + wm + (lane >> 2);
    const int col0 = h * 64 + (lane & 3) * 2;
    #pragma unroll
    for (int nt = 0; nt < 8; nt++) {
        int col = col0 + nt * 8;
        float2 v0, v1;
        v0.x = oacc[nt][0] * inv0;  v0.y = oacc[nt][1] * inv0;
        v1.x = oacc[nt][2] * inv1;  v1.y = oacc[nt][3] * inv1;
        *(float2*)&ctx[((size_t)(b * SQ_ + r0))     * D_ + col] = v0;
        *(float2*)&ctx[((size_t)(b * SQ_ + r0 + 8)) * D_ + col] = v1;
    }
}

// ---------------------------------------------------------------------------
extern "C" void kernel_launch(void* const* d_in, const int* in_sizes, int n_in,
                              void* d_out, int out_size)
{
    const float* query     = (const float*)d_in[0];
    const float* key_value = (const float*)d_in[1];
    const float* Wq        = (const float*)d_in[2];
    const float* bq        = (const float*)d_in[3];
    const float* Wkv       = (const float*)d_in[4];
    const float* bkv       = (const float*)d_in[5];
    const float* Wo        = (const float*)d_in[6];
    const float* bo        = (const float*)d_in[7];
    float* out = (float*)d_out;

    float *Qb, *KVb, *Ctx;
    __nv_bfloat16 *qA, *kA, *cA, *WqB, *WkvB, *WoB;
    __nv_bfloat16 *Qh2, *Ql2, *Kh2, *Kl2, *Vh2, *Vl2;
    cudaGetSymbolAddress((void**)&Qb,   g_Q);
    cudaGetSymbolAddress((void**)&KVb,  g_KV);
    cudaGetSymbolAddress((void**)&Ctx,  g_ctx);
    cudaGetSymbolAddress((void**)&qA,   g_qA);
    cudaGetSymbolAddress((void**)&kA,   g_kA);
    cudaGetSymbolAddress((void**)&cA,   g_cA);
    cudaGetSymbolAddress((void**)&WqB,  g_WqB);
    cudaGetSymbolAddress((void**)&WkvB, g_WkvB);
    cudaGetSymbolAddress((void**)&WoB,  g_WoB);
    cudaGetSymbolAddress((void**)&Qh2,  g_Qh2);  cudaGetSymbolAddress((void**)&Ql2, g_Ql2);
    cudaGetSymbolAddress((void**)&Kh2,  g_Kh2);  cudaGetSymbolAddress((void**)&Kl2, g_Kl2);
    cudaGetSymbolAddress((void**)&Vh2,  g_Vh2);  cudaGetSymbolAddress((void**)&Vl2, g_Vl2);

    cudaFuncSetAttribute(gemm_bulk, cudaFuncAttributeMaxDynamicSharedMemorySize, GEMM_SMEM);
    cudaFuncSetAttribute(attn_tc,   cudaFuncAttributeMaxDynamicSharedMemorySize, ATTN_SMEM);

    // idx 3 = gemm_bulk(Q) lands in the ncu -s 5 window.
    prep_act_tiled<<<2048, 256>>>(query, qA, M_TOT * D_ / 4);                     // 0
    prep_wT_tiled<<<dim3(D_ / 32, D_ / 32), dim3(32, 8)>>>(Wq, WqB, D_, D_);      // 1
    prep_act_tiled<<<2048, 256>>>(key_value, kA, M_TOT * D_ / 4);                 // 2

    gemm_bulk<<<dim3(D_ / 128, M_TOT / 128), 256, GEMM_SMEM>>>(                   // 3
        qA, WqB, bq, Qb, D_, D_);

    prep_wT_tiled<<<dim3(2 * D_ / 32, D_ / 32), dim3(32, 8)>>>(Wkv, WkvB,         // 4
                                                               D_, 2 * D_);
    gemm_bulk<<<dim3(2 * D_ / 128, M_TOT / 128), 256, GEMM_SMEM>>>(               // 5
        kA, WkvB, bkv, KVb, 2 * D_, D_);

    prep_wT_tiled<<<dim3(D_ / 32, D_ / 32), dim3(32, 8)>>>(Wo, WoB, D_, D_);      // 6
    prep_split_qkv<<<2048, 256>>>(Qb, KVb, Qh2, Ql2, Kh2, Kl2, Vh2, Vl2);         // 7

    attn_tc<<<dim3(SQ_ / 128, H_, B_), 256, ATTN_SMEM>>>(                         // 8
        Qh2, Ql2, Kh2, Kl2, Vh2, Vl2, Ctx);

    prep_act_tiled<<<2048, 256>>>(Ctx, cA, M_TOT * D_ / 4);                       // 9
    gemm_bulk<<<dim3(D_ / 128, M_TOT / 128), 256, GEMM_SMEM>>>(                   // 10
        cA, WoB, bo, out, D_, D_);
}

// round 13
// speedup vs baseline: 2.6480x; 1.2280x over previous
#include <cuda_runtime.h>
#include <cuda_bf16.h>
#include <cstdint>

#define B_    4
#define SQ_   2048
#define SK_   2048
#define D_    1024
#define H_    16
#define HD_   64
#define SCALE_ 0.125f
#define M_TOT (B_ * SQ_)   // 8192
#define KSTEPS (D_ / 32)   // 32

// ---------------------------------------------------------------------------
// Scratch (__device__ globals per allocation rules)
// ---------------------------------------------------------------------------
__device__ float g_Q  [(size_t)M_TOT * D_];
__device__ float g_KV [(size_t)M_TOT * 2 * D_];
__device__ float g_ctx[(size_t)M_TOT * D_];

// Pre-swizzled GEMM operand blocks (R12-validated layout)
__device__ __nv_bfloat16 g_qA [(size_t)2 * M_TOT * D_];
__device__ __nv_bfloat16 g_kA [(size_t)2 * M_TOT * D_];
__device__ __nv_bfloat16 g_cA [(size_t)2 * M_TOT * D_];
__device__ __nv_bfloat16 g_WqB [2 * D_ * D_];
__device__ __nv_bfloat16 g_WkvB[2 * D_ * 2 * D_];
__device__ __nv_bfloat16 g_WoB [2 * D_ * D_];

// Pre-swizzled attention blocks:
//  g_Qt:  per (bh, qtile): 32KB = [QH 16K | QL 16K], 128 rows x 128B, SW128
//  g_KVt: per (bh, ktile): 32KB = [KH 8K | KL 8K | VH 8K | VL 8K], 64 rows x 128B
__device__ __nv_bfloat16 g_Qt [(size_t)2 * M_TOT * D_];
__device__ __nv_bfloat16 g_KVt[(size_t)4 * M_TOT * D_];

// ---------------------------------------------------------------------------
// Helpers
// ---------------------------------------------------------------------------
__device__ __forceinline__ uint32_t smem_u32(const void* p) {
    uint32_t a;
    asm("{ .reg .u64 t; cvta.to.shared.u64 t, %1; cvt.u32.u64 %0, t; }" : "=r"(a) : "l"(p));
    return a;
}

#define SW128(off) ((off) ^ (((off) >> 3) & 0x70))

#define CP_BULK(dst, src, bytes, mbar) \
    asm volatile("cp.async.bulk.shared::cta.global.mbarrier::complete_tx::bytes " \
                 "[%0], [%1], %2, [%3];" \
                 :: "r"(dst), "l"(src), "r"(bytes), "r"(mbar) : "memory")

#define MBARRIER_INIT(addr, cnt) \
    asm volatile("mbarrier.init.shared.b64 [%0], %1;" \
                 :: "r"((uint32_t)(addr)), "r"((uint32_t)(cnt)) : "memory")
#define MBARRIER_EXPECT_TX(addr, bytes) \
    asm volatile("mbarrier.arrive.expect_tx.shared.b64 _, [%0], %1;" \
                 :: "r"((uint32_t)(addr)), "r"((uint32_t)(bytes)) : "memory")

#define MBARRIER_WAIT_PARITY(addr, parity) do {                                   \
    uint32_t _m = (uint32_t)(addr);  uint32_t _p = (uint32_t)(parity);            \
    uint32_t _d;                                                                  \
    asm volatile("{\n\t.reg .pred p;\n\t"                                         \
        "mbarrier.try_wait.parity.acquire.cta.shared::cta.b64 p, [%1], %2;\n\t"   \
        "selp.b32 %0, 1, 0, p;\n\t}" : "=r"(_d) : "r"(_m), "r"(_p) : "memory");   \
    if (!_d) {                                                                    \
        asm volatile("{\n\t.reg .pred P1;\n\t"                                    \
            "WL_%=:\n\t"                                                          \
            "mbarrier.try_wait.parity.acquire.cta.shared::cta.b64 P1, [%0], %1, 0x989680;\n\t" \
            "@P1 bra.uni WD_%=;\n\t"                                              \
            "bra.uni WL_%=;\n\t"                                                  \
            "WD_%=:\n\t}" :: "r"(_m), "r"(_p) : "memory");                        \
    }                                                                             \
} while (0)

#define LDSM_X4(r, addr) \
    asm volatile("ldmatrix.sync.aligned.m8n8.x4.shared.b16 {%0,%1,%2,%3}, [%4];" \
                 : "=r"((r)[0]), "=r"((r)[1]), "=r"((r)[2]), "=r"((r)[3]) : "r"(addr))
#define LDSM_X4_T(r, addr) \
    asm volatile("ldmatrix.sync.aligned.m8n8.x4.trans.shared.b16 {%0,%1,%2,%3}, [%4];" \
                 : "=r"((r)[0]), "=r"((r)[1]), "=r"((r)[2]), "=r"((r)[3]) : "r"(addr))
#define LDSM_X2(r, addr) \
    asm volatile("ldmatrix.sync.aligned.m8n8.x2.shared.b16 {%0,%1}, [%2];" \
                 : "=r"((r)[0]), "=r"((r)[1]) : "r"(addr))

#define MMA16816(c, a, b) \
    asm volatile("mma.sync.aligned.m16n8k16.row.col.f32.bf16.bf16.f32 " \
                 "{%0,%1,%2,%3}, {%4,%5,%6,%7}, {%8,%9}, {%0,%1,%2,%3};" \
                 : "+f"((c)[0]), "+f"((c)[1]), "+f"((c)[2]), "+f"((c)[3]) \
                 : "r"((a)[0]), "r"((a)[1]), "r"((a)[2]), "r"((a)[3]), \
                   "r"((b)[0]), "r"((b)[1]))

__device__ __forceinline__ void split2(float x, float y, uint32_t& hi, uint32_t& lo) {
    __nv_bfloat162 h = __floats2bfloat162_rn(x, y);
    float hx = __bfloat162float(h.x), hy = __bfloat162float(h.y);
    __nv_bfloat162 l = __floats2bfloat162_rn(x - hx, y - hy);
    hi = reinterpret_cast<uint32_t&>(h);
    lo = reinterpret_cast<uint32_t&>(l);
}

// ---------------------------------------------------------------------------
// Prep kernels (R12-validated)
// ---------------------------------------------------------------------------
__global__ void prep_act_tiled(const float* __restrict__ X,
                               __nv_bfloat16* __restrict__ out, int n4) {
    int idx = blockIdx.x * blockDim.x + threadIdx.x;
    int stride = gridDim.x * blockDim.x;
    for (; idx < n4; idx += stride) {
        int m  = idx >> 8;
        int k  = (idx & 255) << 2;
        float4 v = ((const float4*)X)[idx];
        uint32_t h0, l0, h1, l1;
        split2(v.x, v.y, h0, l0);
        split2(v.z, v.w, h1, l1);
        int mt = m >> 7, r = m & 127, ks = k >> 5, kk = k & 31;
        char* base = (char*)out + ((size_t)(mt * KSTEPS + ks)) * 16384;
        uint32_t sw = ((uint32_t)(r & 7)) << 4;
        uint32_t dh = (uint32_t)(r * 128 + kk * 2);
        uint2 hv; hv.x = h0; hv.y = h1;
        uint2 lv; lv.x = l0; lv.y = l1;
        *(uint2*)(base + (dh ^ sw))        = hv;
        *(uint2*)(base + ((dh + 64) ^ sw)) = lv;
    }
}

__global__ void prep_wT_tiled(const float* __restrict__ W,
                              __nv_bfloat16* __restrict__ out, int Kd, int Nd) {
    __shared__ float t[32][33];
    int n  = blockIdx.x * 32 + threadIdx.x;
    int k0 = blockIdx.y * 32;
    for (int i = threadIdx.y; i < 32; i += 8)
        t[i][threadIdx.x] = W[(size_t)(k0 + i) * Nd + n];
    __syncthreads();
    int nn = blockIdx.x * 32;
    int kcol = k0 + threadIdx.x;
    int ks = kcol >> 5, kk = kcol & 31;
    for (int i = threadIdx.y; i < 32; i += 8) {
        float v = t[threadIdx.x][i];
        __nv_bfloat16 h = __float2bfloat16_rn(v);
        __nv_bfloat16 l = __float2bfloat16_rn(v - __bfloat162float(h));
        int nrow = nn + i;
        int ntile = nrow >> 7, r = nrow & 127;
        char* base = (char*)out + ((size_t)(ntile * KSTEPS + ks)) * 16384;
        uint32_t sw = ((uint32_t)(r & 7)) << 4;
        uint32_t dh = (uint32_t)(r * 128 + kk * 2);
        *(__nv_bfloat16*)(base + (dh ^ sw))        = h;
        *(__nv_bfloat16*)(base + ((dh + 64) ^ sw)) = l;
    }
}

// Split Q/KV projections into pre-swizzled attention tile blocks.
__global__ void prep_split_tiled(const float* __restrict__ Q, const float* __restrict__ KV,
                                 __nv_bfloat16* __restrict__ Qt,
                                 __nv_bfloat16* __restrict__ KVt) {
    const int total = M_TOT * D_ / 2;
    int idx = blockIdx.x * blockDim.x + threadIdx.x;
    int stride = gridDim.x * blockDim.x;
    for (; idx < total; idx += stride) {
        int d2 = idx & 31;               // pair index, d = d2*2
        int s  = (idx >> 5) & 2047;
        int bh = idx >> 16;
        int h = bh & 15, b = bh >> 4;
        size_t qsrc = ((size_t)(b * SQ_ + s)) * D_ + h * 64 + d2 * 2;
        size_t ksrc = ((size_t)(b * SK_ + s)) * (2 * D_) + h * 64 + d2 * 2;
        float2 qv = *(const float2*)(Q + qsrc);
        float2 kv = *(const float2*)(KV + ksrc);
        float2 vv = *(const float2*)(KV + ksrc + D_);
        uint32_t qhi, qlo, khi, klo, vhi, vlo;
        split2(qv.x, qv.y, qhi, qlo);
        split2(kv.x, kv.y, khi, klo);
        split2(vv.x, vv.y, vhi, vlo);

        // Q block: 128 rows
        {
            int qt = s >> 7, r = s & 127;
            char* qb = (char*)Qt + ((size_t)(bh * 16 + qt)) * 32768;
            uint32_t off = ((uint32_t)(r * 128 + d2 * 4)) ^ (((uint32_t)(r & 7)) << 4);
            *(uint32_t*)(qb + off)          = qhi;
            *(uint32_t*)(qb + 16384 + off)  = qlo;
        }
        // KV block: 64 rows
        {
            int kt = s >> 6, r = s & 63;
            char* kb = (char*)KVt + ((size_t)(bh * 32 + kt)) * 32768;
            uint32_t off = ((uint32_t)(r * 128 + d2 * 4)) ^ (((uint32_t)(r & 7)) << 4);
            *(uint32_t*)(kb + off)          = khi;
            *(uint32_t*)(kb + 8192 + off)   = klo;
            *(uint32_t*)(kb + 16384 + off)  = vhi;
            *(uint32_t*)(kb + 24576 + off)  = vlo;
        }
    }
}

// ---------------------------------------------------------------------------
// GEMM with bulk-copy loads (exact R12-validated kernel)
// ---------------------------------------------------------------------------
#define STAGES  3
#define STAGE_BYTES 32768
#define GEMM_SMEM (2048 + STAGES * STAGE_BYTES)

__global__ __launch_bounds__(256, 2) void gemm_bulk(
    const __nv_bfloat16* __restrict__ gA, const __nv_bfloat16* __restrict__ gB,
    const float* __restrict__ bias, float* __restrict__ C, int N, int K)
{
    extern __shared__ char smraw[];
    const uint32_t raw32  = smem_u32(smraw);
    const uint32_t hdr32  = (raw32 + 1023) & ~1023u;
    const uint32_t stg32  = hdr32 + 1024;

    const int tid  = threadIdx.x;
    const int lane = tid & 31, wid = tid >> 5;
    const int wm0  = (wid & 3) * 32;
    const int wn0  = (wid >> 2) * 64;
    const int m0   = blockIdx.y * 128;
    const int n0   = blockIdx.x * 128;

    const int steps = K / 32;
    const char* srcA = (const char*)gA + (size_t)(blockIdx.y * steps) * 16384;
    const char* srcB = (const char*)gB + (size_t)(blockIdx.x * steps) * 16384;

    if (tid == 0) {
        MBARRIER_INIT(hdr32 + 0, 1);
        MBARRIER_INIT(hdr32 + 8, 1);
        MBARRIER_INIT(hdr32 + 16, 1);
    }
    __syncthreads();
    if (tid == 0) {
        #pragma unroll
        for (int s = 0; s < 2; s++) {
            MBARRIER_EXPECT_TX(hdr32 + s * 8, 32768u);
            CP_BULK(stg32 + s * STAGE_BYTES,          srcA + (size_t)s * 16384, 16384u, hdr32 + s * 8);
            CP_BULK(stg32 + s * STAGE_BYTES + 16384u, srcB + (size_t)s * 16384, 16384u, hdr32 + s * 8);
        }
    }

    float acc[2][8][4];
    #pragma unroll
    for (int mt = 0; mt < 2; mt++)
        #pragma unroll
        for (int nt = 0; nt < 8; nt++)
            #pragma unroll
            for (int r = 0; r < 4; r++) acc[mt][nt][r] = 0.f;

    const uint32_t aRowOff = (uint32_t)((wm0 + (lane & 15)) * 128 + ((lane >> 4) << 4));
    const uint32_t bRowOff = (uint32_t)((wn0 + (lane & 7)) * 128 + (((lane >> 3) & 1) << 4));

    for (int i = 0; i < steps; i++) {
        __syncthreads();
        if (tid == 0 && i + 2 < steps) {
            const int s = (i + 2) % STAGES;
            MBARRIER_EXPECT_TX(hdr32 + s * 8, 32768u);
            CP_BULK(stg32 + s * STAGE_BYTES,          srcA + (size_t)(i + 2) * 16384, 16384u, hdr32 + s * 8);
            CP_BULK(stg32 + s * STAGE_BYTES + 16384u, srcB + (size_t)(i + 2) * 16384, 16384u, hdr32 + s * 8);
        }
        MBARRIER_WAIT_PARITY(hdr32 + (i % STAGES) * 8, (i / STAGES) & 1);

        const uint32_t aB = stg32 + (i % STAGES) * STAGE_BYTES;
        const uint32_t bB = aB + 16384;

        #pragma unroll
        for (int kh = 0; kh < 2; kh++) {
            uint32_t afh[2][4], afl[2][4];
            #pragma unroll
            for (int mt = 0; mt < 2; mt++) {
                uint32_t off = aRowOff + (uint32_t)(mt * 16 * 128 + kh * 32);
                LDSM_X4(afh[mt], aB + SW128(off));
                LDSM_X4(afl[mt], aB + SW128(off + 64));
            }
            #pragma unroll
            for (int nt = 0; nt < 8; nt++) {
                uint32_t off = bRowOff + (uint32_t)(nt * 8 * 128 + kh * 32);
                uint32_t bfh[2], bfl[2];
                LDSM_X2(bfh, bB + SW128(off));
                LDSM_X2(bfl, bB + SW128(off + 64));
                #pragma unroll
                for (int mt = 0; mt < 2; mt++) {
                    MMA16816(acc[mt][nt], afh[mt], bfh);
                    MMA16816(acc[mt][nt], afh[mt], bfl);
                    MMA16816(acc[mt][nt], afl[mt], bfh);
                }
            }
        }
    }

    const int erow = lane >> 2, ecol = (lane & 3) * 2;
    #pragma unroll
    for (int nt = 0; nt < 8; nt++) {
        int col = n0 + wn0 + nt * 8 + ecol;
        float2 bv = *(const float2*)&bias[col];
        #pragma unroll
        for (int mt = 0; mt < 2; mt++) {
            int row = m0 + wm0 + mt * 16 + erow;
            float2 v0, v1;
            v0.x = acc[mt][nt][0] + bv.x;  v0.y = acc[mt][nt][1] + bv.y;
            v1.x = acc[mt][nt][2] + bv.x;  v1.y = acc[mt][nt][3] + bv.y;
            *(float2*)&C[(size_t)row * N + col]       = v0;
            *(float2*)&C[(size_t)(row + 8) * N + col] = v1;
        }
    }
}

// ---------------------------------------------------------------------------
// Attention with bulk-copy loads (R5-validated compute core)
// Smem: hdr (3 mbarriers) | Q [QH 16K|QL 16K] | 2 stages x 32KB
// ---------------------------------------------------------------------------
#define ATTN_SMEM (2048 + 3 * 32768)

__global__ __launch_bounds__(256, 2) void attn_bulk(
    const __nv_bfloat16* __restrict__ Qt, const __nv_bfloat16* __restrict__ KVt,
    float* __restrict__ ctx)
{
    extern __shared__ char smraw[];
    const uint32_t raw32  = smem_u32(smraw);
    const uint32_t hdr32  = (raw32 + 1023) & ~1023u;
    const uint32_t qsm    = hdr32 + 1024;          // QH, QL @ +16384
    #define ASTG(s) (qsm + 32768u + (uint32_t)(s) * 32768u)

    const int tid  = threadIdx.x;
    const int lane = tid & 31, wid = tid >> 5;
    const int h  = blockIdx.y, b = blockIdx.z;
    const int bh = b * H_ + h;
    const int q0 = blockIdx.x * 128;

    const char* qsrc = (const char*)Qt  + ((size_t)(bh * 16 + blockIdx.x)) * 32768;
    const char* ksrc = (const char*)KVt + ((size_t)(bh * 32)) * 32768;

    if (tid == 0) {
        MBARRIER_INIT(hdr32 + 0, 1);    // Q
        MBARRIER_INIT(hdr32 + 8, 1);    // stage 0
        MBARRIER_INIT(hdr32 + 16, 1);   // stage 1
    }
    __syncthreads();
    if (tid == 0) {
        MBARRIER_EXPECT_TX(hdr32 + 0, 32768u);
        CP_BULK(qsm, qsrc, 32768u, hdr32 + 0);
        MBARRIER_EXPECT_TX(hdr32 + 8, 32768u);
        CP_BULK(ASTG(0), ksrc, 32768u, hdr32 + 8);
    }

    float oacc[8][4];
    #pragma unroll
    for (int nt = 0; nt < 8; nt++)
        #pragma unroll
        for (int r = 0; r < 4; r++) oacc[nt][r] = 0.f;
    float mrow[2] = {-1e30f, -1e30f}, lrowsum[2] = {0.f, 0.f};

    const float c2 = SCALE_ * 1.44269504088896340736f;
    const int wm = wid * 16;
    const uint32_t aOff = (uint32_t)((wm + (lane & 15)) * 128 + ((lane >> 4) << 4));
    const uint32_t kOff = (uint32_t)((lane & 15) * 128 + ((lane >> 4) << 4));
    const uint32_t vOff = (uint32_t)((lane & 15) * 128 + ((lane >> 4) << 4));

    MBARRIER_WAIT_PARITY(hdr32 + 0, 0);            // Q resident

    const int iters = SK_ / 64;
    for (int i = 0; i < iters; i++) {
        __syncthreads();   // readers of stage (i+1)&1 (iter i-1) are done
        if (tid == 0 && i + 1 < iters) {
            const int s = (i + 1) & 1;
            MBARRIER_EXPECT_TX(hdr32 + 8 + s * 8, 32768u);
            CP_BULK(ASTG(s), ksrc + (size_t)(i + 1) * 32768, 32768u, hdr32 + 8 + s * 8);
        }
        MBARRIER_WAIT_PARITY(hdr32 + 8 + (i & 1) * 8, (i >> 1) & 1);

        const uint32_t KH = ASTG(i & 1), KL = KH + 8192, VH = KH + 16384, VL = KH + 24576;
        const uint32_t QH = qsm, QL = qsm + 16384;

        float sacc[8][4];
        #pragma unroll
        for (int nt = 0; nt < 8; nt++)
            #pragma unroll
            for (int r = 0; r < 4; r++) sacc[nt][r] = 0.f;

        #pragma unroll
        for (int kc = 0; kc < 4; kc++) {
            uint32_t afh[4], afl[4];
            LDSM_X4(afh, QH + SW128(aOff + kc * 32));
            LDSM_X4(afl, QL + SW128(aOff + kc * 32));
            #pragma unroll
            for (int ntp = 0; ntp < 4; ntp++) {
                uint32_t b4h[4], b4l[4];
                uint32_t off = kOff + (uint32_t)(ntp * 2048 + kc * 32);
                LDSM_X4(b4h, KH + SW128(off));
                LDSM_X4(b4l, KL + SW128(off));
                uint32_t bh0[2] = {b4h[0], b4h[2]}, bh1[2] = {b4h[1], b4h[3]};
                uint32_t bl0[2] = {b4l[0], b4l[2]}, bl1[2] = {b4l[1], b4l[3]};
                MMA16816(sacc[2 * ntp],     afh, bh0);
                MMA16816(sacc[2 * ntp],     afh, bl0);
                MMA16816(sacc[2 * ntp],     afl, bh0);
                MMA16816(sacc[2 * ntp + 1], afh, bh1);
                MMA16816(sacc[2 * ntp + 1], afh, bl1);
                MMA16816(sacc[2 * ntp + 1], afl, bh1);
            }
        }

        float fac[2];
        #pragma unroll
        for (int j = 0; j < 2; j++) {
            float tmax = -1e30f;
            #pragma unroll
            for (int nt = 0; nt < 8; nt++)
                tmax = fmaxf(tmax, fmaxf(sacc[nt][2 * j], sacc[nt][2 * j + 1]));
            tmax = fmaxf(tmax, __shfl_xor_sync(0xffffffffu, tmax, 1));
            tmax = fmaxf(tmax, __shfl_xor_sync(0xffffffffu, tmax, 2));
            float mn = fmaxf(mrow[j], tmax);
            fac[j] = exp2f((mrow[j] - mn) * c2);
            mrow[j] = mn;
            float tsum = 0.f;
            #pragma unroll
            for (int nt = 0; nt < 8; nt++) {
                float p0 = exp2f((sacc[nt][2 * j]     - mn) * c2);
                float p1 = exp2f((sacc[nt][2 * j + 1] - mn) * c2);
                sacc[nt][2 * j] = p0; sacc[nt][2 * j + 1] = p1;
                tsum += p0 + p1;
            }
            tsum += __shfl_xor_sync(0xffffffffu, tsum, 1);
            tsum += __shfl_xor_sync(0xffffffffu, tsum, 2);
            lrowsum[j] = lrowsum[j] * fac[j] + tsum;
            #pragma unroll
            for (int nt = 0; nt < 8; nt++) {
                oacc[nt][2 * j]     *= fac[j];
                oacc[nt][2 * j + 1] *= fac[j];
            }
        }

        #pragma unroll
        for (int kc = 0; kc < 4; kc++) {
            uint32_t ah[4], al[4];
            split2(sacc[2 * kc][0],     sacc[2 * kc][1],     ah[0], al[0]);
            split2(sacc[2 * kc][2],     sacc[2 * kc][3],     ah[1], al[1]);
            split2(sacc[2 * kc + 1][0], sacc[2 * kc + 1][1], ah[2], al[2]);
            split2(sacc[2 * kc + 1][2], sacc[2 * kc + 1][3], ah[3], al[3]);
            #pragma unroll
            for (int ntp = 0; ntp < 4; ntp++) {
                uint32_t v4h[4], v4l[4];
                uint32_t off = vOff + (uint32_t)(kc * 2048 + ntp * 32);
                LDSM_X4_T(v4h, VH + SW128(off));
                LDSM_X4_T(v4l, VL + SW128(off));
                uint32_t bh0[2] = {v4h[0], v4h[1]}, bh1[2] = {v4h[2], v4h[3]};
                uint32_t bl0[2] = {v4l[0], v4l[1]}, bl1[2] = {v4l[2], v4l[3]};
                MMA16816(oacc[2 * ntp],     ah, bh0);
                MMA16816(oacc[2 * ntp],     ah, bl0);
                MMA16816(oacc[2 * ntp],     al, bh0);
                MMA16816(oacc[2 * ntp + 1], ah, bh1);
                MMA16816(oacc[2 * ntp + 1], ah, bl1);
                MMA16816(oacc[2 * ntp + 1], al, bh1);
            }
        }
    }

    const float inv0 = 1.f / lrowsum[0], inv1 = 1.f / lrowsum[1];
    const int r0 = q0 + wm + (lane >> 2);
    const int col0 = h * 64 + (lane & 3) * 2;
    #pragma unroll
    for (int nt = 0; nt < 8; nt++) {
        int col = col0 + nt * 8;
        float2 v0, v1;
        v0.x = oacc[nt][0] * inv0;  v0.y = oacc[nt][1] * inv0;
        v1.x = oacc[nt][2] * inv1;  v1.y = oacc[nt][3] * inv1;
        *(float2*)&ctx[((size_t)(b * SQ_ + r0))     * D_ + col] = v0;
        *(float2*)&ctx[((size_t)(b * SQ_ + r0 + 8)) * D_ + col] = v1;
    }
}

// ---------------------------------------------------------------------------
extern "C" void kernel_launch(void* const* d_in, const int* in_sizes, int n_in,
                              void* d_out, int out_size)
{
    const float* query     = (const float*)d_in[0];
    const float* key_value = (const float*)d_in[1];
    const float* Wq        = (const float*)d_in[2];
    const float* bq        = (const float*)d_in[3];
    const float* Wkv       = (const float*)d_in[4];
    const float* bkv       = (const float*)d_in[5];
    const float* Wo        = (const float*)d_in[6];
    const float* bo        = (const float*)d_in[7];
    float* out = (float*)d_out;

    float *Qb, *KVb, *Ctx;
    __nv_bfloat16 *qA, *kA, *cA, *WqB, *WkvB, *WoB, *Qt, *KVt;
    cudaGetSymbolAddress((void**)&Qb,   g_Q);
    cudaGetSymbolAddress((void**)&KVb,  g_KV);
    cudaGetSymbolAddress((void**)&Ctx,  g_ctx);
    cudaGetSymbolAddress((void**)&qA,   g_qA);
    cudaGetSymbolAddress((void**)&kA,   g_kA);
    cudaGetSymbolAddress((void**)&cA,   g_cA);
    cudaGetSymbolAddress((void**)&WqB,  g_WqB);
    cudaGetSymbolAddress((void**)&WkvB, g_WkvB);
    cudaGetSymbolAddress((void**)&WoB,  g_WoB);
    cudaGetSymbolAddress((void**)&Qt,   g_Qt);
    cudaGetSymbolAddress((void**)&KVt,  g_KVt);

    cudaFuncSetAttribute(gemm_bulk, cudaFuncAttributeMaxDynamicSharedMemorySize, GEMM_SMEM);
    cudaFuncSetAttribute(attn_bulk, cudaFuncAttributeMaxDynamicSharedMemorySize, ATTN_SMEM);

    // idx 3 = gemm_bulk(Q) lands in the ncu -s 5 window.
    prep_act_tiled<<<2048, 256>>>(query, qA, M_TOT * D_ / 4);                     // 0
    prep_wT_tiled<<<dim3(D_ / 32, D_ / 32), dim3(32, 8)>>>(Wq, WqB, D_, D_);      // 1
    prep_act_tiled<<<2048, 256>>>(key_value, kA, M_TOT * D_ / 4);                 // 2

    gemm_bulk<<<dim3(D_ / 128, M_TOT / 128), 256, GEMM_SMEM>>>(                   // 3
        qA, WqB, bq, Qb, D_, D_);

    prep_wT_tiled<<<dim3(2 * D_ / 32, D_ / 32), dim3(32, 8)>>>(Wkv, WkvB,         // 4
                                                               D_, 2 * D_);
    gemm_bulk<<<dim3(2 * D_ / 128, M_TOT / 128), 256, GEMM_SMEM>>>(               // 5
        kA, WkvB, bkv, KVb, 2 * D_, D_);

    prep_wT_tiled<<<dim3(D_ / 32, D_ / 32), dim3(32, 8)>>>(Wo, WoB, D_, D_);      // 6
    prep_split_tiled<<<2048, 256>>>(Qb, KVb, Qt, KVt);                            // 7

    attn_bulk<<<dim3(SQ_ / 128, H_, B_), 256, ATTN_SMEM>>>(Qt, KVt, Ctx);         // 8

    prep_act_tiled<<<2048, 256>>>(Ctx, cA, M_TOT * D_ / 4);                       // 9
    gemm_bulk<<<dim3(D_ / 128, M_TOT / 128), 256, GEMM_SMEM>>>(                   // 10
        cA, WoB, bo, out, D_, D_);
}

// round 15
// speedup vs baseline: 2.6813x; 1.0125x over previous
#include <cuda_runtime.h>
#include <cuda_bf16.h>
#include <cstdint>

#define B_    4
#define SQ_   2048
#define SK_   2048
#define D_    1024
#define H_    16
#define HD_   64
#define SCALE_ 0.125f
#define M_TOT (B_ * SQ_)   // 8192
#define KSTEPS (D_ / 32)   // 32

// ---------------------------------------------------------------------------
// Scratch (__device__ globals per allocation rules)
// ---------------------------------------------------------------------------
__device__ float g_Q  [(size_t)M_TOT * D_];
__device__ float g_KV [(size_t)M_TOT * 2 * D_];
__device__ float g_ctx[(size_t)M_TOT * D_];

__device__ __nv_bfloat16 g_qA [(size_t)2 * M_TOT * D_];
__device__ __nv_bfloat16 g_kA [(size_t)2 * M_TOT * D_];
__device__ __nv_bfloat16 g_cA [(size_t)2 * M_TOT * D_];
__device__ __nv_bfloat16 g_WqB [2 * D_ * D_];
__device__ __nv_bfloat16 g_WkvB[2 * D_ * 2 * D_];
__device__ __nv_bfloat16 g_WoB [2 * D_ * D_];

__device__ __nv_bfloat16 g_Qt [(size_t)2 * M_TOT * D_];
__device__ __nv_bfloat16 g_KVt[(size_t)4 * M_TOT * D_];

// ---------------------------------------------------------------------------
// Helpers
// ---------------------------------------------------------------------------
__device__ __forceinline__ uint32_t smem_u32(const void* p) {
    uint32_t a;
    asm("{ .reg .u64 t; cvta.to.shared.u64 t, %1; cvt.u32.u64 %0, t; }" : "=r"(a) : "l"(p));
    return a;
}

#define SW128(off) ((off) ^ (((off) >> 3) & 0x70))

#define CP_BULK(dst, src, bytes, mbar) \
    asm volatile("cp.async.bulk.shared::cta.global.mbarrier::complete_tx::bytes " \
                 "[%0], [%1], %2, [%3];" \
                 :: "r"(dst), "l"(src), "r"(bytes), "r"(mbar) : "memory")

#define MBARRIER_INIT(addr, cnt) \
    asm volatile("mbarrier.init.shared.b64 [%0], %1;" \
                 :: "r"((uint32_t)(addr)), "r"((uint32_t)(cnt)) : "memory")
#define MBARRIER_EXPECT_TX(addr, bytes) \
    asm volatile("mbarrier.arrive.expect_tx.shared.b64 _, [%0], %1;" \
                 :: "r"((uint32_t)(addr)), "r"((uint32_t)(bytes)) : "memory")

#define MBARRIER_WAIT_PARITY(addr, parity) do {                                   \
    uint32_t _m = (uint32_t)(addr);  uint32_t _p = (uint32_t)(parity);            \
    uint32_t _d;                                                                  \
    asm volatile("{\n\t.reg .pred p;\n\t"                                         \
        "mbarrier.try_wait.parity.acquire.cta.shared::cta.b64 p, [%1], %2;\n\t"   \
        "selp.b32 %0, 1, 0, p;\n\t}" : "=r"(_d) : "r"(_m), "r"(_p) : "memory");   \
    if (!_d) {                                                                    \
        asm volatile("{\n\t.reg .pred P1;\n\t"                                    \
            "WL_%=:\n\t"                                                          \
            "mbarrier.try_wait.parity.acquire.cta.shared::cta.b64 P1, [%0], %1, 0x989680;\n\t" \
            "@P1 bra.uni WD_%=;\n\t"                                              \
            "bra.uni WL_%=;\n\t"                                                  \
            "WD_%=:\n\t}" :: "r"(_m), "r"(_p) : "memory");                        \
    }                                                                             \
} while (0)

#define LDSM_X4(r, addr) \
    asm volatile("ldmatrix.sync.aligned.m8n8.x4.shared.b16 {%0,%1,%2,%3}, [%4];" \
                 : "=r"((r)[0]), "=r"((r)[1]), "=r"((r)[2]), "=r"((r)[3]) : "r"(addr))
#define LDSM_X4_T(r, addr) \
    asm volatile("ldmatrix.sync.aligned.m8n8.x4.trans.shared.b16 {%0,%1,%2,%3}, [%4];" \
                 : "=r"((r)[0]), "=r"((r)[1]), "=r"((r)[2]), "=r"((r)[3]) : "r"(addr))
#define LDSM_X2(r, addr) \
    asm volatile("ldmatrix.sync.aligned.m8n8.x2.shared.b16 {%0,%1}, [%2];" \
                 : "=r"((r)[0]), "=r"((r)[1]) : "r"(addr))

#define MMA16816(c, a, b) \
    asm volatile("mma.sync.aligned.m16n8k16.row.col.f32.bf16.bf16.f32 " \
                 "{%0,%1,%2,%3}, {%4,%5,%6,%7}, {%8,%9}, {%0,%1,%2,%3};" \
                 : "+f"((c)[0]), "+f"((c)[1]), "+f"((c)[2]), "+f"((c)[3]) \
                 : "r"((a)[0]), "r"((a)[1]), "r"((a)[2]), "r"((a)[3]), \
                   "r"((b)[0]), "r"((b)[1]))

__device__ __forceinline__ void split2(float x, float y, uint32_t& hi, uint32_t& lo) {
    __nv_bfloat162 h = __floats2bfloat162_rn(x, y);
    float hx = __bfloat162float(h.x), hy = __bfloat162float(h.y);
    __nv_bfloat162 l = __floats2bfloat162_rn(x - hx, y - hy);
    hi = reinterpret_cast<uint32_t&>(h);
    lo = reinterpret_cast<uint32_t&>(l);
}

// ---------------------------------------------------------------------------
// Prep kernels
// ---------------------------------------------------------------------------
__device__ __forceinline__ void act_tile_store(const float4 v, int m, int k,
                                               __nv_bfloat16* out) {
    uint32_t h0, l0, h1, l1;
    split2(v.x, v.y, h0, l0);
    split2(v.z, v.w, h1, l1);
    int mt = m >> 7, r = m & 127, ks = k >> 5, kk = k & 31;
    char* base = (char*)out + ((size_t)(mt * KSTEPS + ks)) * 16384;
    uint32_t sw = ((uint32_t)(r & 7)) << 4;
    uint32_t dh = (uint32_t)(r * 128 + kk * 2);
    uint2 hv; hv.x = h0; hv.y = h1;
    uint2 lv; lv.x = l0; lv.y = l1;
    *(uint2*)(base + (dh ^ sw))        = hv;
    *(uint2*)(base + ((dh + 64) ^ sw)) = lv;
}

__global__ void prep_act_tiled(const float* __restrict__ X,
                               __nv_bfloat16* __restrict__ out, int n4) {
    int idx = blockIdx.x * blockDim.x + threadIdx.x;
    int stride = gridDim.x * blockDim.x;
    for (; idx < n4; idx += stride)
        act_tile_store(((const float4*)X)[idx], idx >> 8, (idx & 255) << 2, out);
}

// query + key_value splits in ONE launch (independent work merged)
__global__ void prep_act2(const float* __restrict__ Xq, const float* __restrict__ Xk,
                          __nv_bfloat16* __restrict__ outq,
                          __nv_bfloat16* __restrict__ outk, int n4) {
    int idx = blockIdx.x * blockDim.x + threadIdx.x;
    int stride = gridDim.x * blockDim.x;
    const int total = 2 * n4;
    for (; idx < total; idx += stride) {
        if (idx < n4)
            act_tile_store(((const float4*)Xq)[idx], idx >> 8, (idx & 255) << 2, outq);
        else {
            int i = idx - n4;
            act_tile_store(((const float4*)Xk)[i], i >> 8, (i & 255) << 2, outk);
        }
    }
}

__device__ __forceinline__ void wT_tile_body(const float* W, __nv_bfloat16* out,
                                             int Kd, int Nd) {
    __shared__ float t[32][33];
    int n  = blockIdx.x * 32 + threadIdx.x;
    int k0 = blockIdx.y * 32;
    for (int i = threadIdx.y; i < 32; i += 8)
        t[i][threadIdx.x] = W[(size_t)(k0 + i) * Nd + n];
    __syncthreads();
    int nn = blockIdx.x * 32;
    int kcol = k0 + threadIdx.x;
    int ks = kcol >> 5, kk = kcol & 31;
    for (int i = threadIdx.y; i < 32; i += 8) {
        float v = t[threadIdx.x][i];
        __nv_bfloat16 h = __float2bfloat16_rn(v);
        __nv_bfloat16 l = __float2bfloat16_rn(v - __bfloat162float(h));
        int nrow = nn + i;
        int ntile = nrow >> 7, r = nrow & 127;
        char* base = (char*)out + ((size_t)(ntile * KSTEPS + ks)) * 16384;
        uint32_t sw = ((uint32_t)(r & 7)) << 4;
        uint32_t dh = (uint32_t)(r * 128 + kk * 2);
        *(__nv_bfloat16*)(base + (dh ^ sw))        = h;
        *(__nv_bfloat16*)(base + ((dh + 64) ^ sw)) = l;
    }
}

__global__ void prep_wT_tiled(const float* __restrict__ W,
                              __nv_bfloat16* __restrict__ out, int Kd, int Nd) {
    wT_tile_body(W, out, Kd, Nd);
}

// Wq + Wkv preps in ONE launch (grid.z selects problem)
__global__ void prep_wT2(const float* __restrict__ Wq_, __nv_bfloat16* __restrict__ WqB_,
                         const float* __restrict__ Wkv_, __nv_bfloat16* __restrict__ WkvB_) {
    if (blockIdx.z == 0) {
        if (blockIdx.x >= 32) return;         // Nd = 1024 -> 32 n-blocks
        wT_tile_body(Wq_, WqB_, D_, D_);
    } else {
        wT_tile_body(Wkv_, WkvB_, D_, 2 * D_);
    }
}

__global__ void prep_split_tiled(const float* __restrict__ Q, const float* __restrict__ KV,
                                 __nv_bfloat16* __restrict__ Qt,
                                 __nv_bfloat16* __restrict__ KVt) {
    const int total = M_TOT * D_ / 2;
    int idx = blockIdx.x * blockDim.x + threadIdx.x;
    int stride = gridDim.x * blockDim.x;
    for (; idx < total; idx += stride) {
        int d2 = idx & 31;
        int s  = (idx >> 5) & 2047;
        int bh = idx >> 16;
        int h = bh & 15, b = bh >> 4;
        size_t qsrc = ((size_t)(b * SQ_ + s)) * D_ + h * 64 + d2 * 2;
        size_t ksrc = ((size_t)(b * SK_ + s)) * (2 * D_) + h * 64 + d2 * 2;
        float2 qv = *(const float2*)(Q + qsrc);
        float2 kv = *(const float2*)(KV + ksrc);
        float2 vv = *(const float2*)(KV + ksrc + D_);
        uint32_t qhi, qlo, khi, klo, vhi, vlo;
        split2(qv.x, qv.y, qhi, qlo);
        split2(kv.x, kv.y, khi, klo);
        split2(vv.x, vv.y, vhi, vlo);
        {
            int qt = s >> 7, r = s & 127;
            char* qb = (char*)Qt + ((size_t)(bh * 16 + qt)) * 32768;
            uint32_t off = ((uint32_t)(r * 128 + d2 * 4)) ^ (((uint32_t)(r & 7)) << 4);
            *(uint32_t*)(qb + off)          = qhi;
            *(uint32_t*)(qb + 16384 + off)  = qlo;
        }
        {
            int kt = s >> 6, r = s & 63;
            char* kb = (char*)KVt + ((size_t)(bh * 32 + kt)) * 32768;
            uint32_t off = ((uint32_t)(r * 128 + d2 * 4)) ^ (((uint32_t)(r & 7)) << 4);
            *(uint32_t*)(kb + off)          = khi;
            *(uint32_t*)(kb + 8192 + off)   = klo;
            *(uint32_t*)(kb + 16384 + off)  = vhi;
            *(uint32_t*)(kb + 24576 + off)  = vlo;
        }
    }
}

// ---------------------------------------------------------------------------
// GEMM core (R12-validated) as a device function; two launch wrappers:
//   gemm_bulk  — single problem (O projection)
//   gemm_dual  — Q-proj + KV-proj merged into one 1536-block launch
// ---------------------------------------------------------------------------
#define STAGES  3
#define STAGE_BYTES 32768
#define GEMM_SMEM (2048 + STAGES * STAGE_BYTES)

__device__ __forceinline__ void gemm_body(
    const __nv_bfloat16* gA, const __nv_bfloat16* gB,
    const float* bias, float* C, int N, int K, int bx, int by)
{
    extern __shared__ char smraw[];
    const uint32_t raw32  = smem_u32(smraw);
    const uint32_t hdr32  = (raw32 + 1023) & ~1023u;
    const uint32_t stg32  = hdr32 + 1024;

    const int tid  = threadIdx.x;
    const int lane = tid & 31, wid = tid >> 5;
    const int wm0  = (wid & 3) * 32;
    const int wn0  = (wid >> 2) * 64;
    const int m0   = by * 128;
    const int n0   = bx * 128;

    const int steps = K / 32;
    const char* srcA = (const char*)gA + (size_t)(by * steps) * 16384;
    const char* srcB = (const char*)gB + (size_t)(bx * steps) * 16384;

    if (tid == 0) {
        MBARRIER_INIT(hdr32 + 0, 1);
        MBARRIER_INIT(hdr32 + 8, 1);
        MBARRIER_INIT(hdr32 + 16, 1);
    }
    __syncthreads();
    if (tid == 0) {
        #pragma unroll
        for (int s = 0; s < 2; s++) {
            MBARRIER_EXPECT_TX(hdr32 + s * 8, 32768u);
            CP_BULK(stg32 + s * STAGE_BYTES,          srcA + (size_t)s * 16384, 16384u, hdr32 + s * 8);
            CP_BULK(stg32 + s * STAGE_BYTES + 16384u, srcB + (size_t)s * 16384, 16384u, hdr32 + s * 8);
        }
    }

    float acc[2][8][4];
    #pragma unroll
    for (int mt = 0; mt < 2; mt++)
        #pragma unroll
        for (int nt = 0; nt < 8; nt++)
            #pragma unroll
            for (int r = 0; r < 4; r++) acc[mt][nt][r] = 0.f;

    const uint32_t aRowOff = (uint32_t)((wm0 + (lane & 15)) * 128 + ((lane >> 4) << 4));
    const uint32_t bRowOff = (uint32_t)((wn0 + (lane & 7)) * 128 + (((lane >> 3) & 1) << 4));

    for (int i = 0; i < steps; i++) {
        __syncthreads();
        if (tid == 0 && i + 2 < steps) {
            const int s = (i + 2) % STAGES;
            MBARRIER_EXPECT_TX(hdr32 + s * 8, 32768u);
            CP_BULK(stg32 + s * STAGE_BYTES,          srcA + (size_t)(i + 2) * 16384, 16384u, hdr32 + s * 8);
            CP_BULK(stg32 + s * STAGE_BYTES + 16384u, srcB + (size_t)(i + 2) * 16384, 16384u, hdr32 + s * 8);
        }
        MBARRIER_WAIT_PARITY(hdr32 + (i % STAGES) * 8, (i / STAGES) & 1);

        const uint32_t aB = stg32 + (i % STAGES) * STAGE_BYTES;
        const uint32_t bB = aB + 16384;

        #pragma unroll
        for (int kh = 0; kh < 2; kh++) {
            uint32_t afh[2][4], afl[2][4];
            #pragma unroll
            for (int mt = 0; mt < 2; mt++) {
                uint32_t off = aRowOff + (uint32_t)(mt * 16 * 128 + kh * 32);
                LDSM_X4(afh[mt], aB + SW128(off));
                LDSM_X4(afl[mt], aB + SW128(off + 64));
            }
            #pragma unroll
            for (int nt = 0; nt < 8; nt++) {
                uint32_t off = bRowOff + (uint32_t)(nt * 8 * 128 + kh * 32);
                uint32_t bfh[2], bfl[2];
                LDSM_X2(bfh, bB + SW128(off));
                LDSM_X2(bfl, bB + SW128(off + 64));
                #pragma unroll
                for (int mt = 0; mt < 2; mt++) {
                    MMA16816(acc[mt][nt], afh[mt], bfh);
                    MMA16816(acc[mt][nt], afh[mt], bfl);
                    MMA16816(acc[mt][nt], afl[mt], bfh);
                }
            }
        }
    }

    const int erow = lane >> 2, ecol = (lane & 3) * 2;
    #pragma unroll
    for (int nt = 0; nt < 8; nt++) {
        int col = n0 + wn0 + nt * 8 + ecol;
        float2 bv = *(const float2*)&bias[col];
        #pragma unroll
        for (int mt = 0; mt < 2; mt++) {
            int row = m0 + wm0 + mt * 16 + erow;
            float2 v0, v1;
            v0.x = acc[mt][nt][0] + bv.x;  v0.y = acc[mt][nt][1] + bv.y;
            v1.x = acc[mt][nt][2] + bv.x;  v1.y = acc[mt][nt][3] + bv.y;
            *(float2*)&C[(size_t)row * N + col]       = v0;
            *(float2*)&C[(size_t)(row + 8) * N + col] = v1;
        }
    }
}

__global__ __launch_bounds__(256, 2) void gemm_bulk(
    const __nv_bfloat16* __restrict__ gA, const __nv_bfloat16* __restrict__ gB,
    const float* __restrict__ bias, float* __restrict__ C, int N, int K)
{
    gemm_body(gA, gB, bias, C, N, K, blockIdx.x, blockIdx.y);
}

// Q-proj (512 tiles) + KV-proj (1024 tiles) in one 1536-block launch.
__global__ __launch_bounds__(256, 2) void gemm_dual(
    const __nv_bfloat16* __restrict__ qA, const __nv_bfloat16* __restrict__ WqB,
    const float* __restrict__ bq, float* __restrict__ Qb,
    const __nv_bfloat16* __restrict__ kA, const __nv_bfloat16* __restrict__ WkvB,
    const float* __restrict__ bkv, float* __restrict__ KVb)
{
    int t = blockIdx.x;
    if (t < 512)
        gemm_body(qA, WqB, bq, Qb, D_, D_, t & 7, t >> 3);
    else {
        t -= 512;
        gemm_body(kA, WkvB, bkv, KVb, 2 * D_, D_, t & 15, t >> 4);
    }
}

// ---------------------------------------------------------------------------
// Attention with bulk-copy loads (exact R13-validated kernel)
// ---------------------------------------------------------------------------
#define ATTN_SMEM (2048 + 3 * 32768)

__global__ __launch_bounds__(256, 2) void attn_bulk(
    const __nv_bfloat16* __restrict__ Qt, const __nv_bfloat16* __restrict__ KVt,
    float* __restrict__ ctx)
{
    extern __shared__ char smraw[];
    const uint32_t raw32  = smem_u32(smraw);
    const uint32_t hdr32  = (raw32 + 1023) & ~1023u;
    const uint32_t qsm    = hdr32 + 1024;
    #define ASTG(s) (qsm + 32768u + (uint32_t)(s) * 32768u)

    const int tid  = threadIdx.x;
    const int lane = tid & 31, wid = tid >> 5;
    const int h  = blockIdx.y, b = blockIdx.z;
    const int bh = b * H_ + h;
    const int q0 = blockIdx.x * 128;

    const char* qsrc = (const char*)Qt  + ((size_t)(bh * 16 + blockIdx.x)) * 32768;
    const char* ksrc = (const char*)KVt + ((size_t)(bh * 32)) * 32768;

    if (tid == 0) {
        MBARRIER_INIT(hdr32 + 0, 1);
        MBARRIER_INIT(hdr32 + 8, 1);
        MBARRIER_INIT(hdr32 + 16, 1);
    }
    __syncthreads();
    if (tid == 0) {
        MBARRIER_EXPECT_TX(hdr32 + 0, 32768u);
        CP_BULK(qsm, qsrc, 32768u, hdr32 + 0);
        MBARRIER_EXPECT_TX(hdr32 + 8, 32768u);
        CP_BULK(ASTG(0), ksrc, 32768u, hdr32 + 8);
    }

    float oacc[8][4];
    #pragma unroll
    for (int nt = 0; nt < 8; nt++)
        #pragma unroll
        for (int r = 0; r < 4; r++) oacc[nt][r] = 0.f;
    float mrow[2] = {-1e30f, -1e30f}, lrowsum[2] = {0.f, 0.f};

    const float c2 = SCALE_ * 1.44269504088896340736f;
    const int wm = wid * 16;
    const uint32_t aOff = (uint32_t)((wm + (lane & 15)) * 128 + ((lane >> 4) << 4));
    const uint32_t kOff = (uint32_t)((lane & 15) * 128 + ((lane >> 4) << 4));
    const uint32_t vOff = (uint32_t)((lane & 15) * 128 + ((lane >> 4) << 4));

    MBARRIER_WAIT_PARITY(hdr32 + 0, 0);

    const int iters = SK_ / 64;
    for (int i = 0; i < iters; i++) {
        __syncthreads();
        if (tid == 0 && i + 1 < iters) {
            const int s = (i + 1) & 1;
            MBARRIER_EXPECT_TX(hdr32 + 8 + s * 8, 32768u);
            CP_BULK(ASTG(s), ksrc + (size_t)(i + 1) * 32768, 32768u, hdr32 + 8 + s * 8);
        }
        MBARRIER_WAIT_PARITY(hdr32 + 8 + (i & 1) * 8, (i >> 1) & 1);

        const uint32_t KH = ASTG(i & 1), KL = KH + 8192, VH = KH + 16384, VL = KH + 24576;
        const uint32_t QH = qsm, QL = qsm + 16384;

        float sacc[8][4];
        #pragma unroll
        for (int nt = 0; nt < 8; nt++)
            #pragma unroll
            for (int r = 0; r < 4; r++) sacc[nt][r] = 0.f;

        #pragma unroll
        for (int kc = 0; kc < 4; kc++) {
            uint32_t afh[4], afl[4];
            LDSM_X4(afh, QH + SW128(aOff + kc * 32));
            LDSM_X4(afl, QL + SW128(aOff + kc * 32));
            #pragma unroll
            for (int ntp = 0; ntp < 4; ntp++) {
                uint32_t b4h[4], b4l[4];
                uint32_t off = kOff + (uint32_t)(ntp * 2048 + kc * 32);
                LDSM_X4(b4h, KH + SW128(off));
                LDSM_X4(b4l, KL + SW128(off));
                uint32_t bh0[2] = {b4h[0], b4h[2]}, bh1[2] = {b4h[1], b4h[3]};
                uint32_t bl0[2] = {b4l[0], b4l[2]}, bl1[2] = {b4l[1], b4l[3]};
                MMA16816(sacc[2 * ntp],     afh, bh0);
                MMA16816(sacc[2 * ntp],     afh, bl0);
                MMA16816(sacc[2 * ntp],     afl, bh0);
                MMA16816(sacc[2 * ntp + 1], afh, bh1);
                MMA16816(sacc[2 * ntp + 1], afh, bl1);
                MMA16816(sacc[2 * ntp + 1], afl, bh1);
            }
        }

        float fac[2];
        #pragma unroll
        for (int j = 0; j < 2; j++) {
            float tmax = -1e30f;
            #pragma unroll
            for (int nt = 0; nt < 8; nt++)
                tmax = fmaxf(tmax, fmaxf(sacc[nt][2 * j], sacc[nt][2 * j + 1]));
            tmax = fmaxf(tmax, __shfl_xor_sync(0xffffffffu, tmax, 1));
            tmax = fmaxf(tmax, __shfl_xor_sync(0xffffffffu, tmax, 2));
            float mn = fmaxf(mrow[j], tmax);
            fac[j] = exp2f((mrow[j] - mn) * c2);
            mrow[j] = mn;
            float tsum = 0.f;
            #pragma unroll
            for (int nt = 0; nt < 8; nt++) {
                float p0 = exp2f((sacc[nt][2 * j]     - mn) * c2);
                float p1 = exp2f((sacc[nt][2 * j + 1] - mn) * c2);
                sacc[nt][2 * j] = p0; sacc[nt][2 * j + 1] = p1;
                tsum += p0 + p1;
            }
            tsum += __shfl_xor_sync(0xffffffffu, tsum, 1);
            tsum += __shfl_xor_sync(0xffffffffu, tsum, 2);
            lrowsum[j] = lrowsum[j] * fac[j] + tsum;
            #pragma unroll
            for (int nt = 0; nt < 8; nt++) {
                oacc[nt][2 * j]     *= fac[j];
                oacc[nt][2 * j + 1] *= fac[j];
            }
        }

        #pragma unroll
        for (int kc = 0; kc < 4; kc++) {
            uint32_t ah[4], al[4];
            split2(sacc[2 * kc][0],     sacc[2 * kc][1],     ah[0], al[0]);
            split2(sacc[2 * kc][2],     sacc[2 * kc][3],     ah[1], al[1]);
            split2(sacc[2 * kc + 1][0], sacc[2 * kc + 1][1], ah[2], al[2]);
            split2(sacc[2 * kc + 1][2], sacc[2 * kc + 1][3], ah[3], al[3]);
            #pragma unroll
            for (int ntp = 0; ntp < 4; ntp++) {
                uint32_t v4h[4], v4l[4];
                uint32_t off = vOff + (uint32_t)(kc * 2048 + ntp * 32);
                LDSM_X4_T(v4h, VH + SW128(off));
                LDSM_X4_T(v4l, VL + SW128(off));
                uint32_t bh0[2] = {v4h[0], v4h[1]}, bh1[2] = {v4h[2], v4h[3]};
                uint32_t bl0[2] = {v4l[0], v4l[1]}, bl1[2] = {v4l[2], v4l[3]};
                MMA16816(oacc[2 * ntp],     ah, bh0);
                MMA16816(oacc[2 * ntp],     ah, bl0);
                MMA16816(oacc[2 * ntp],     al, bh0);
                MMA16816(oacc[2 * ntp + 1], ah, bh1);
                MMA16816(oacc[2 * ntp + 1], ah, bl1);
                MMA16816(oacc[2 * ntp + 1], al, bh1);
            }
        }
    }

    const float inv0 = 1.f / lrowsum[0], inv1 = 1.f / lrowsum[1];
    const int r0 = q0 + wm + (lane >> 2);
    const int col0 = h * 64 + (lane & 3) * 2;
    #pragma unroll
    for (int nt = 0; nt < 8; nt++) {
        int col = col0 + nt * 8;
        float2 v0, v1;
        v0.x = oacc[nt][0] * inv0;  v0.y = oacc[nt][1] * inv0;
        v1.x = oacc[nt][2] * inv1;  v1.y = oacc[nt][3] * inv1;
        *(float2*)&ctx[((size_t)(b * SQ_ + r0))     * D_ + col] = v0;
        *(float2*)&ctx[((size_t)(b * SQ_ + r0 + 8)) * D_ + col] = v1;
    }
}

// ---------------------------------------------------------------------------
extern "C" void kernel_launch(void* const* d_in, const int* in_sizes, int n_in,
                              void* d_out, int out_size)
{
    const float* query     = (const float*)d_in[0];
    const float* key_value = (const float*)d_in[1];
    const float* Wq        = (const float*)d_in[2];
    const float* bq        = (const float*)d_in[3];
    const float* Wkv       = (const float*)d_in[4];
    const float* bkv       = (const float*)d_in[5];
    const float* Wo        = (const float*)d_in[6];
    const float* bo        = (const float*)d_in[7];
    float* out = (float*)d_out;

    float *Qb, *KVb, *Ctx;
    __nv_bfloat16 *qA, *kA, *cA, *WqB, *WkvB, *WoB, *Qt, *KVt;
    cudaGetSymbolAddress((void**)&Qb,   g_Q);
    cudaGetSymbolAddress((void**)&KVb,  g_KV);
    cudaGetSymbolAddress((void**)&Ctx,  g_ctx);
    cudaGetSymbolAddress((void**)&qA,   g_qA);
    cudaGetSymbolAddress((void**)&kA,   g_kA);
    cudaGetSymbolAddress((void**)&cA,   g_cA);
    cudaGetSymbolAddress((void**)&WqB,  g_WqB);
    cudaGetSymbolAddress((void**)&WkvB, g_WkvB);
    cudaGetSymbolAddress((void**)&WoB,  g_WoB);
    cudaGetSymbolAddress((void**)&Qt,   g_Qt);
    cudaGetSymbolAddress((void**)&KVt,  g_KVt);

    cudaFuncSetAttribute(gemm_bulk, cudaFuncAttributeMaxDynamicSharedMemorySize, GEMM_SMEM);
    cudaFuncSetAttribute(gemm_dual, cudaFuncAttributeMaxDynamicSharedMemorySize, GEMM_SMEM);
    cudaFuncSetAttribute(attn_bulk, cudaFuncAttributeMaxDynamicSharedMemorySize, ATTN_SMEM);

    // Merged launches (no streams — grid-level concurrency instead).
    prep_act2<<<2048, 256>>>(query, key_value, qA, kA, M_TOT * D_ / 4);           // 0
    prep_wT2<<<dim3(2 * D_ / 32, D_ / 32, 2), dim3(32, 8)>>>(Wq, WqB, Wkv, WkvB); // 1
    prep_wT_tiled<<<dim3(D_ / 32, D_ / 32), dim3(32, 8)>>>(Wo, WoB, D_, D_);      // 2

    gemm_dual<<<1536, 256, GEMM_SMEM>>>(qA, WqB, bq, Qb, kA, WkvB, bkv, KVb);     // 3

    prep_split_tiled<<<2048, 256>>>(Qb, KVb, Qt, KVt);                            // 4
    attn_bulk<<<dim3(SQ_ / 128, H_, B_), 256, ATTN_SMEM>>>(Qt, KVt, Ctx);         // 5
    prep_act_tiled<<<2048, 256>>>(Ctx, cA, M_TOT * D_ / 4);                       // 6
    gemm_bulk<<<dim3(D_ / 128, M_TOT / 128), 256, GEMM_SMEM>>>(                   // 7
        cA, WoB, bo, out, D_, D_);
}